// round 5
// baseline (speedup 1.0000x reference)
#include <cuda_runtime.h>
#include <cuda_fp16.h>
#include <math.h>
#include <stdint.h>

// ---------------------------------------------------------------------------
// Problem constants
// ---------------------------------------------------------------------------
#define TOKENS   32768      // 16 * 2048
#define DIM      1024
#define HEADS    8
#define DHEAD    128
#define LN_EPS   1e-5f

// GEMM tiling: CTA 128x256, K-chunk 64, warp tile 64x64, 8 warps (2m x 4n)
#define BM       128
#define BN       256
#define BK       64
#define NKK      16           // 1024 / 64 K-chunks
#define STAGES   3
#define SA       144          // smem row stride (128B data + 16B pad)
#define ROWS_PER_STAGE (BM + BM + BN)        // Ahi(128) + Alo(128) + B(256) = 512
#define STAGEB   (ROWS_PER_STAGE * SA)       // 73728
#define SMEMB    (STAGES * STAGEB)           // 221184

// ---------------------------------------------------------------------------
// Scratch (device globals; cudaMalloc forbidden)
// ---------------------------------------------------------------------------
__device__ __half g_qn_hi [TOKENS * DIM];
__device__ __half g_qn_lo [TOKENS * DIM];
__device__ __half g_kvn_hi[TOKENS * DIM];
__device__ __half g_kvn_lo[TOKENS * DIM];
__device__ __half g_wq_h  [DIM * DIM];
__device__ __half g_wkv_h [2 * DIM * DIM];
__device__ __half g_wo_h  [DIM * DIM];
__device__ __half g_query [TOKENS * DIM];          // fp16 intermediates now
__device__ __half g_kvproj[TOKENS * 2 * DIM];
__device__ __half g_ctx_hi[TOKENS * DIM];
__device__ __half g_ctx_lo[TOKENS * DIM];

// ---------------------------------------------------------------------------
// PTX helpers (plain sm_80-level; harness PTX target is sm_103 non-'a')
// ---------------------------------------------------------------------------
__device__ __forceinline__ uint32_t smem_u32(const void* p) {
    uint32_t a;
    asm("{ .reg .u64 t; cvta.to.shared.u64 t, %1; cvt.u32.u64 %0, t; }" : "=r"(a) : "l"(p));
    return a;
}

__device__ __forceinline__ void cp16(uint32_t dst, const void* src) {
    asm volatile("cp.async.cg.shared.global [%0], [%1], 16;" :: "r"(dst), "l"(src));
}
#define CP_COMMIT() asm volatile("cp.async.commit_group;" ::: "memory")
#define CP_WAIT1()  asm volatile("cp.async.wait_group 1;" ::: "memory")

__device__ __forceinline__ void ldsm4(uint32_t* r, uint32_t addr) {
    asm volatile("ldmatrix.sync.aligned.m8n8.x4.shared.b16 {%0,%1,%2,%3}, [%4];"
                 : "=r"(r[0]), "=r"(r[1]), "=r"(r[2]), "=r"(r[3]) : "r"(addr));
}

__device__ __forceinline__ void mma16816h(float* d, const uint32_t* a, uint32_t b0, uint32_t b1) {
    asm volatile("mma.sync.aligned.m16n8k16.row.col.f32.f16.f16.f32 "
                 "{%0,%1,%2,%3}, {%4,%5,%6,%7}, {%8,%9}, {%0,%1,%2,%3};"
                 : "+f"(d[0]), "+f"(d[1]), "+f"(d[2]), "+f"(d[3])
                 : "r"(a[0]), "r"(a[1]), "r"(a[2]), "r"(a[3]), "r"(b0), "r"(b1));
}

// epilogue store: fp32 or fp16 output
__device__ __forceinline__ void store2(float* p, float a, float b)  { *(float2*)p  = make_float2(a, b); }
__device__ __forceinline__ void store2(__half* p, float a, float b) { *(__half2*)p = __floats2half2_rn(a, b); }

// ---------------------------------------------------------------------------
// Fused LayerNorm (both q and kv) + fp16 hi/lo split.  grid (TOKENS, 2).
// ---------------------------------------------------------------------------
__global__ __launch_bounds__(256)
void ln_split2_kernel(const float* __restrict__ q,  const float* __restrict__ kv,
                      const float* __restrict__ gm, const float* __restrict__ bm,
                      const float* __restrict__ gl, const float* __restrict__ bl,
                      __half* __restrict__ qhi, __half* __restrict__ qlo,
                      __half* __restrict__ khi, __half* __restrict__ klo) {
    const int row = blockIdx.x;
    const int sel = blockIdx.y;
    const float* x     = sel ? kv  : q;
    const float* gamma = sel ? gl  : gm;
    const float* beta  = sel ? bl  : bm;
    __half* hi = sel ? khi : qhi;
    __half* lo = sel ? klo : qlo;

    const int tid = threadIdx.x;
    float4 v = ((const float4*)(x + (size_t)row * DIM))[tid];

    float s  = v.x + v.y + v.z + v.w;
    float sq = v.x * v.x + v.y * v.y + v.z * v.z + v.w * v.w;
    #pragma unroll
    for (int o = 16; o > 0; o >>= 1) {
        s  += __shfl_xor_sync(0xffffffffu, s,  o);
        sq += __shfl_xor_sync(0xffffffffu, sq, o);
    }
    __shared__ float rs[8], rq[8];
    const int wid = tid >> 5, lane = tid & 31;
    if (lane == 0) { rs[wid] = s; rq[wid] = sq; }
    __syncthreads();
    float tot = 0.f, totq = 0.f;
    #pragma unroll
    for (int i = 0; i < 8; i++) { tot += rs[i]; totq += rq[i]; }

    const float mu   = tot * (1.0f / DIM);
    const float var  = totq * (1.0f / DIM) - mu * mu;
    const float rinv = rsqrtf(var + LN_EPS);

    float4 g = ((const float4*)gamma)[tid];
    float4 b = ((const float4*)beta)[tid];
    float o0 = (v.x - mu) * rinv * g.x + b.x;
    float o1 = (v.y - mu) * rinv * g.y + b.y;
    float o2 = (v.z - mu) * rinv * g.z + b.z;
    float o3 = (v.w - mu) * rinv * g.w + b.w;

    __half h0 = __float2half_rn(o0), h1 = __float2half_rn(o1);
    __half h2 = __float2half_rn(o2), h3 = __float2half_rn(o3);
    __half l0 = __float2half_rn(o0 - __half2float(h0));
    __half l1 = __float2half_rn(o1 - __half2float(h1));
    __half l2 = __float2half_rn(o2 - __half2float(h2));
    __half l3 = __float2half_rn(o3 - __half2float(h3));

    __half2* hp = (__half2*)(hi + (size_t)row * DIM);
    __half2* lp = (__half2*)(lo + (size_t)row * DIM);
    hp[2 * tid]     = __halves2half2(h0, h1);
    hp[2 * tid + 1] = __halves2half2(h2, h3);
    lp[2 * tid]     = __halves2half2(l0, l1);
    lp[2 * tid + 1] = __halves2half2(l2, l3);
}

// ---------------------------------------------------------------------------
// All three weights -> fp16 in one launch
// ---------------------------------------------------------------------------
__global__ __launch_bounds__(256)
void wconv_kernel(const float* __restrict__ Wq, const float* __restrict__ Wkv,
                  const float* __restrict__ Wo,
                  __half* __restrict__ wq, __half* __restrict__ wkv, __half* __restrict__ wo) {
    const int i = blockIdx.x * 256 + threadIdx.x;    // 0 .. 4*DIM*DIM-1
    if (i < DIM * DIM)               wq[i]                 = __float2half_rn(Wq[i]);
    else if (i < 3 * DIM * DIM)      wkv[i - DIM * DIM]    = __float2half_rn(Wkv[i - DIM * DIM]);
    else                             wo[i - 3 * DIM * DIM] = __float2half_rn(Wo[i - 3 * DIM * DIM]);
}

// ---------------------------------------------------------------------------
// fp16 2-term GEMM:  C[M,N] = (Ahi + Alo)[M,K] * B[N,K]^T, fp32 accum.
// CTA 128x256, 8 warps of 64x64, 3-stage cp.async pipeline.
// OutT = __half (query/kvproj) or float (final output).
// ---------------------------------------------------------------------------
template <typename OutT>
__global__ __launch_bounds__(256, 1)
void gemm_fp16_2term(const __half* __restrict__ Ah, const __half* __restrict__ Al,
                     const __half* __restrict__ B, OutT* __restrict__ C, int ldc) {
    extern __shared__ char smem[];
    const uint32_t sbase = smem_u32(smem);
    const int tid  = threadIdx.x;
    const int wid  = tid >> 5;
    const int lane = tid & 31;
    const int bm = blockIdx.y * BM;
    const int bn = blockIdx.x * BN;
    const int m_base = (wid >> 2) * 64;   // 0 or 64
    const int n_base = (wid & 3) * 64;    // 0,64,128,192

    float acc[4][8][4];
    #pragma unroll
    for (int i = 0; i < 4; i++)
        #pragma unroll
        for (int j = 0; j < 8; j++)
            #pragma unroll
            for (int k = 0; k < 4; k++) acc[i][j][k] = 0.f;

    auto load_stage = [&](int kk, int s) {
        const uint32_t st = sbase + s * STAGEB;
        #pragma unroll
        for (int i = 0; i < 16; i++) {
            const int idx = tid + i * 256;
            const int row = idx >> 3;          // 0..511
            const int c8  = idx & 7;
            const __half* src;
            if (row < 128)      src = Ah + (size_t)(bm + row) * DIM + kk * BK + c8 * 8;
            else if (row < 256) src = Al + (size_t)(bm + row - 128) * DIM + kk * BK + c8 * 8;
            else                src = B  + (size_t)(bn + row - 256) * DIM + kk * BK + c8 * 8;
            cp16(st + row * SA + c8 * 16, src);
        }
        CP_COMMIT();
    };

    load_stage(0, 0);
    load_stage(1, 1);

    const int lrow = lane & 15;
    const int lsel = (lane >> 4) * 16;    // 0 or 16 bytes

    for (int kk = 0; kk < NKK; kk++) {
        CP_WAIT1();
        __syncthreads();
        if (kk + 2 < NKK) load_stage(kk + 2, (kk + 2) % STAGES);
        else              CP_COMMIT();     // empty group keeps wait_group 1 sound

        const uint32_t st     = sbase + (kk % STAGES) * STAGEB;
        const uint32_t ahaddr = st + (m_base + lrow) * SA + lsel;
        const uint32_t aladdr = ahaddr + 128 * SA;
        const uint32_t baddr  = st + 256 * SA + (n_base + lrow) * SA + lsel;

        #pragma unroll
        for (int ks = 0; ks < 4; ks++) {
            // load ALL fragments first -> max scheduling freedom for ptxas
            uint32_t br[4][4], arh[4][4], arl[4][4];
            #pragma unroll
            for (int ni = 0; ni < 4; ni++) ldsm4(br[ni],  baddr  + ni * 16 * SA + ks * 32);
            #pragma unroll
            for (int mi = 0; mi < 4; mi++) ldsm4(arh[mi], ahaddr + mi * 16 * SA + ks * 32);
            #pragma unroll
            for (int mi = 0; mi < 4; mi++) ldsm4(arl[mi], aladdr + mi * 16 * SA + ks * 32);

            #pragma unroll
            for (int mi = 0; mi < 4; mi++)
                #pragma unroll
                for (int nj = 0; nj < 8; nj++)
                    mma16816h(acc[mi][nj], arh[mi],
                              br[nj >> 1][nj & 1], br[nj >> 1][2 + (nj & 1)]);
            #pragma unroll
            for (int mi = 0; mi < 4; mi++)
                #pragma unroll
                for (int nj = 0; nj < 8; nj++)
                    mma16816h(acc[mi][nj], arl[mi],
                              br[nj >> 1][nj & 1], br[nj >> 1][2 + (nj & 1)]);
        }
    }

    // epilogue
    const int g  = lane >> 2;
    const int t2 = (lane & 3) * 2;
    #pragma unroll
    for (int mi = 0; mi < 4; mi++) {
        const int row = bm + m_base + mi * 16 + g;
        OutT* crow = C + (size_t)row * ldc + bn + n_base + t2;
        #pragma unroll
        for (int nj = 0; nj < 8; nj++) {
            store2(crow + nj * 8,                   acc[mi][nj][0], acc[mi][nj][1]);
            store2(crow + (size_t)8 * ldc + nj * 8, acc[mi][nj][2], acc[mi][nj][3]);
        }
    }
}

// ---------------------------------------------------------------------------
// Per-token attention over HEADS axis; fp16 in, split-fp16 context out.
// ---------------------------------------------------------------------------
__global__ __launch_bounds__(128)
void attn_kernel(const __half* __restrict__ query,
                 const __half* __restrict__ kvproj,
                 __half* __restrict__ ctx_hi,
                 __half* __restrict__ ctx_lo) {
    const int t = blockIdx.x;
    const int tid = threadIdx.x;
    __shared__ float qs[DIM], ks[DIM], vs[DIM];
    __shared__ float w[HEADS * HEADS];
    __shared__ float sc[HEADS * HEADS];

    // each thread loads 8 halves (16B) per array segment and converts
    {
        const uint4* qp = (const uint4*)(query + (size_t)t * DIM);
        const uint4* kp = (const uint4*)(kvproj + (size_t)t * 2 * DIM);
        const uint4* vp = kp + DIM / 8;
        uint4 uq = qp[tid], uk = kp[tid], uv = vp[tid];
        const __half2* hq = (const __half2*)&uq;
        const __half2* hk = (const __half2*)&uk;
        const __half2* hv = (const __half2*)&uv;
        #pragma unroll
        for (int i = 0; i < 4; i++) {
            float2 f;
            f = __half22float2(hq[i]); qs[tid * 8 + 2 * i] = f.x; qs[tid * 8 + 2 * i + 1] = f.y;
            f = __half22float2(hk[i]); ks[tid * 8 + 2 * i] = f.x; ks[tid * 8 + 2 * i + 1] = f.y;
            f = __half22float2(hv[i]); vs[tid * 8 + 2 * i] = f.x; vs[tid * 8 + 2 * i + 1] = f.y;
        }
    }
    __syncthreads();

    if (tid < HEADS * HEADS) {
        const int h = tid >> 3, g = tid & 7;
        const float* qq = qs + h * DHEAD;
        const float* kk = ks + g * DHEAD;
        float s = 0.f;
        #pragma unroll 8
        for (int d = 0; d < DHEAD; d++) s += qq[d] * kk[d];
        sc[tid] = s * 0.08838834764831845f;   // 1/sqrt(128)
    }
    __syncthreads();

    if (tid < HEADS) {
        float m = -1e30f;
        #pragma unroll
        for (int g = 0; g < HEADS; g++) m = fmaxf(m, sc[tid * 8 + g]);
        float e[HEADS], sum = 0.f;
        #pragma unroll
        for (int g = 0; g < HEADS; g++) { e[g] = expf(sc[tid * 8 + g] - m); sum += e[g]; }
        const float inv = 1.0f / sum;
        #pragma unroll
        for (int g = 0; g < HEADS; g++) w[tid * 8 + g] = e[g] * inv;
    }
    __syncthreads();

    #pragma unroll
    for (int h = 0; h < HEADS; h++) {
        float a = 0.f;
        #pragma unroll
        for (int g = 0; g < HEADS; g++) a += w[h * 8 + g] * vs[g * DHEAD + tid];
        const size_t idx = (size_t)t * DIM + h * DHEAD + tid;
        __half hv = __float2half_rn(a);
        ctx_hi[idx] = hv;
        ctx_lo[idx] = __float2half_rn(a - __half2float(hv));
    }
}

// ---------------------------------------------------------------------------
// Host side.  Launch order (for ncu -s 5): ln(0), wconv(1), gemm1(2),
// gemm2(3), attn(4), gemm3(5) -> profile captures gemm3.
// ---------------------------------------------------------------------------
extern "C" void kernel_launch(void* const* d_in, const int* in_sizes, int n_in,
                              void* d_out, int out_size) {
    const float* q       = (const float*)d_in[0];
    const float* kv      = (const float*)d_in[1];
    const float* gamma_m = (const float*)d_in[2];
    const float* beta_m  = (const float*)d_in[3];
    const float* gamma_l = (const float*)d_in[4];
    const float* beta_l  = (const float*)d_in[5];
    const float* Wq      = (const float*)d_in[6];
    const float* Wkv     = (const float*)d_in[7];
    const float* Wo      = (const float*)d_in[8];
    float* out = (float*)d_out;

    void *qn_hi, *qn_lo, *kvn_hi, *kvn_lo, *wq_h, *wkv_h, *wo_h;
    void *query, *kvproj, *ctx_hi, *ctx_lo;
    cudaGetSymbolAddress(&qn_hi,  g_qn_hi);   cudaGetSymbolAddress(&qn_lo,  g_qn_lo);
    cudaGetSymbolAddress(&kvn_hi, g_kvn_hi);  cudaGetSymbolAddress(&kvn_lo, g_kvn_lo);
    cudaGetSymbolAddress(&wq_h,   g_wq_h);    cudaGetSymbolAddress(&wkv_h,  g_wkv_h);
    cudaGetSymbolAddress(&wo_h,   g_wo_h);
    cudaGetSymbolAddress(&query,  g_query);   cudaGetSymbolAddress(&kvproj, g_kvproj);
    cudaGetSymbolAddress(&ctx_hi, g_ctx_hi);  cudaGetSymbolAddress(&ctx_lo, g_ctx_lo);

    cudaFuncSetAttribute(gemm_fp16_2term<__half>, cudaFuncAttributeMaxDynamicSharedMemorySize, SMEMB);
    cudaFuncSetAttribute(gemm_fp16_2term<float>,  cudaFuncAttributeMaxDynamicSharedMemorySize, SMEMB);

    // 0: fused LN + split for q and kv
    ln_split2_kernel<<<dim3(TOKENS, 2), 256>>>(q, kv, gamma_m, beta_m, gamma_l, beta_l,
                                               (__half*)qn_hi, (__half*)qn_lo,
                                               (__half*)kvn_hi, (__half*)kvn_lo);
    // 1: all weights -> fp16
    wconv_kernel<<<(4 * DIM * DIM) / 256, 256>>>(Wq, Wkv, Wo,
                                                 (__half*)wq_h, (__half*)wkv_h, (__half*)wo_h);

    // 2: query = qn @ Wq^T   [32768,1024] (fp16 out)
    gemm_fp16_2term<__half><<<dim3(DIM / BN, TOKENS / BM), 256, SMEMB>>>(
        (const __half*)qn_hi, (const __half*)qn_lo, (const __half*)wq_h,
        (__half*)query, DIM);
    // 3: kvproj = kvn @ Wkv^T  [32768,2048] (fp16 out)
    gemm_fp16_2term<__half><<<dim3(2 * DIM / BN, TOKENS / BM), 256, SMEMB>>>(
        (const __half*)kvn_hi, (const __half*)kvn_lo, (const __half*)wkv_h,
        (__half*)kvproj, 2 * DIM);

    // 4: attention
    attn_kernel<<<TOKENS, 128>>>((const __half*)query, (const __half*)kvproj,
                                 (__half*)ctx_hi, (__half*)ctx_lo);

    // 5: out = ctx @ Wo^T   [32768,1024] (fp32 out)  <- ncu target
    gemm_fp16_2term<float><<<dim3(DIM / BN, TOKENS / BM), 256, SMEMB>>>(
        (const __half*)ctx_hi, (const __half*)ctx_lo, (const __half*)wo_h,
        out, DIM);
}

// round 7
// speedup vs baseline: 1.5643x; 1.5643x over previous
#include <cuda_runtime.h>
#include <cuda_fp16.h>
#include <math.h>
#include <stdint.h>

// ---------------------------------------------------------------------------
// Problem constants
// ---------------------------------------------------------------------------
#define TOKENS   32768      // 16 * 2048
#define DIM      1024
#define HEADS    8
#define DHEAD    128
#define LN_EPS   1e-5f

// GEMM tiling: CTA 128x256, K-chunk 64, warp tile 64x64, 8 warps (2m x 4n)
#define BM       128
#define BN       256
#define BK       64
#define NKK      16           // 1024 / 64 K-chunks
#define STAGES   3
#define SA       144          // smem row stride (128B data + 16B pad)
#define ROWS_PER_STAGE (BM + BM + BN)        // Ahi(128) + Alo(128) + B(256) = 512
#define STAGEB   (ROWS_PER_STAGE * SA)       // 73728
#define SMEMB    (STAGES * STAGEB)           // 221184

// ---------------------------------------------------------------------------
// Scratch (device globals; cudaMalloc forbidden)
// ---------------------------------------------------------------------------
__device__ __half g_qn_hi [TOKENS * DIM];
__device__ __half g_qn_lo [TOKENS * DIM];
__device__ __half g_kvn_hi[TOKENS * DIM];
__device__ __half g_kvn_lo[TOKENS * DIM];
__device__ __half g_wq_h  [DIM * DIM];
__device__ __half g_wkv_h [2 * DIM * DIM];
__device__ __half g_wo_h  [DIM * DIM];
__device__ __half g_query [TOKENS * DIM];          // fp16 intermediates
__device__ __half g_kvproj[TOKENS * 2 * DIM];
__device__ __half g_ctx_hi[TOKENS * DIM];
__device__ __half g_ctx_lo[TOKENS * DIM];

// ---------------------------------------------------------------------------
// PTX helpers (plain sm_80-level; harness PTX target is sm_103 non-'a')
// ---------------------------------------------------------------------------
__device__ __forceinline__ uint32_t smem_u32(const void* p) {
    uint32_t a;
    asm("{ .reg .u64 t; cvta.to.shared.u64 t, %1; cvt.u32.u64 %0, t; }" : "=r"(a) : "l"(p));
    return a;
}

__device__ __forceinline__ void cp16(uint32_t dst, const void* src) {
    asm volatile("cp.async.cg.shared.global [%0], [%1], 16;" :: "r"(dst), "l"(src));
}
#define CP_COMMIT() asm volatile("cp.async.commit_group;" ::: "memory")
#define CP_WAIT1()  asm volatile("cp.async.wait_group 1;" ::: "memory")

__device__ __forceinline__ void ldsm4(uint32_t* r, uint32_t addr) {
    asm volatile("ldmatrix.sync.aligned.m8n8.x4.shared.b16 {%0,%1,%2,%3}, [%4];"
                 : "=r"(r[0]), "=r"(r[1]), "=r"(r[2]), "=r"(r[3]) : "r"(addr));
}

__device__ __forceinline__ void mma16816h(float* d, const uint32_t* a, uint32_t b0, uint32_t b1) {
    asm volatile("mma.sync.aligned.m16n8k16.row.col.f32.f16.f16.f32 "
                 "{%0,%1,%2,%3}, {%4,%5,%6,%7}, {%8,%9}, {%0,%1,%2,%3};"
                 : "+f"(d[0]), "+f"(d[1]), "+f"(d[2]), "+f"(d[3])
                 : "r"(a[0]), "r"(a[1]), "r"(a[2]), "r"(a[3]), "r"(b0), "r"(b1));
}

// epilogue store: fp32 or fp16 output
__device__ __forceinline__ void store2(float* p, float a, float b)  { *(float2*)p  = make_float2(a, b); }
__device__ __forceinline__ void store2(__half* p, float a, float b) { *(__half2*)p = __floats2half2_rn(a, b); }

// ---------------------------------------------------------------------------
// Fused LayerNorm (both q and kv) + fp16 hi/lo split.  grid (TOKENS, 2).
// ---------------------------------------------------------------------------
__global__ __launch_bounds__(256)
void ln_split2_kernel(const float* __restrict__ q,  const float* __restrict__ kv,
                      const float* __restrict__ gm, const float* __restrict__ bm,
                      const float* __restrict__ gl, const float* __restrict__ bl,
                      __half* __restrict__ qhi, __half* __restrict__ qlo,
                      __half* __restrict__ khi, __half* __restrict__ klo) {
    const int row = blockIdx.x;
    const int sel = blockIdx.y;
    const float* x     = sel ? kv  : q;
    const float* gamma = sel ? gl  : gm;
    const float* beta  = sel ? bl  : bm;
    __half* hi = sel ? khi : qhi;
    __half* lo = sel ? klo : qlo;

    const int tid = threadIdx.x;
    float4 v = ((const float4*)(x + (size_t)row * DIM))[tid];

    float s  = v.x + v.y + v.z + v.w;
    float sq = v.x * v.x + v.y * v.y + v.z * v.z + v.w * v.w;
    #pragma unroll
    for (int o = 16; o > 0; o >>= 1) {
        s  += __shfl_xor_sync(0xffffffffu, s,  o);
        sq += __shfl_xor_sync(0xffffffffu, sq, o);
    }
    __shared__ float rs[8], rq[8];
    const int wid = tid >> 5, lane = tid & 31;
    if (lane == 0) { rs[wid] = s; rq[wid] = sq; }
    __syncthreads();
    float tot = 0.f, totq = 0.f;
    #pragma unroll
    for (int i = 0; i < 8; i++) { tot += rs[i]; totq += rq[i]; }

    const float mu   = tot * (1.0f / DIM);
    const float var  = totq * (1.0f / DIM) - mu * mu;
    const float rinv = rsqrtf(var + LN_EPS);

    float4 g = ((const float4*)gamma)[tid];
    float4 b = ((const float4*)beta)[tid];
    float o0 = (v.x - mu) * rinv * g.x + b.x;
    float o1 = (v.y - mu) * rinv * g.y + b.y;
    float o2 = (v.z - mu) * rinv * g.z + b.z;
    float o3 = (v.w - mu) * rinv * g.w + b.w;

    __half h0 = __float2half_rn(o0), h1 = __float2half_rn(o1);
    __half h2 = __float2half_rn(o2), h3 = __float2half_rn(o3);
    __half l0 = __float2half_rn(o0 - __half2float(h0));
    __half l1 = __float2half_rn(o1 - __half2float(h1));
    __half l2 = __float2half_rn(o2 - __half2float(h2));
    __half l3 = __float2half_rn(o3 - __half2float(h3));

    __half2* hp = (__half2*)(hi + (size_t)row * DIM);
    __half2* lp = (__half2*)(lo + (size_t)row * DIM);
    hp[2 * tid]     = __halves2half2(h0, h1);
    hp[2 * tid + 1] = __halves2half2(h2, h3);
    lp[2 * tid]     = __halves2half2(l0, l1);
    lp[2 * tid + 1] = __halves2half2(l2, l3);
}

// ---------------------------------------------------------------------------
// All three weights -> fp16 in one launch
// ---------------------------------------------------------------------------
__global__ __launch_bounds__(256)
void wconv_kernel(const float* __restrict__ Wq, const float* __restrict__ Wkv,
                  const float* __restrict__ Wo,
                  __half* __restrict__ wq, __half* __restrict__ wkv, __half* __restrict__ wo) {
    const int i = blockIdx.x * 256 + threadIdx.x;    // 0 .. 4*DIM*DIM-1
    if (i < DIM * DIM)               wq[i]                 = __float2half_rn(Wq[i]);
    else if (i < 3 * DIM * DIM)      wkv[i - DIM * DIM]    = __float2half_rn(Wkv[i - DIM * DIM]);
    else                             wo[i - 3 * DIM * DIM] = __float2half_rn(Wo[i - 3 * DIM * DIM]);
}

// ---------------------------------------------------------------------------
// fp16 2-term GEMM:  C[M,N] = (Ahi + Alo)[M,K] * B[N,K]^T, fp32 accum.
// CTA 128x256, 8 warps of 64x64, 3-stage cp.async pipeline.
// Mainloop = round-4 interleave: ldsm(B,Ah) -> 32 MMA -> ldsm(Al) -> 32 MMA.
// ---------------------------------------------------------------------------
template <typename OutT>
__global__ __launch_bounds__(256, 1)
void gemm_fp16_2term(const __half* __restrict__ Ah, const __half* __restrict__ Al,
                     const __half* __restrict__ B, OutT* __restrict__ C, int ldc) {
    extern __shared__ char smem[];
    const uint32_t sbase = smem_u32(smem);
    const int tid  = threadIdx.x;
    const int wid  = tid >> 5;
    const int lane = tid & 31;
    const int bm = blockIdx.y * BM;
    const int bn = blockIdx.x * BN;
    const int m_base = (wid >> 2) * 64;   // 0 or 64
    const int n_base = (wid & 3) * 64;    // 0,64,128,192

    float acc[4][8][4];
    #pragma unroll
    for (int i = 0; i < 4; i++)
        #pragma unroll
        for (int j = 0; j < 8; j++)
            #pragma unroll
            for (int k = 0; k < 4; k++) acc[i][j][k] = 0.f;

    auto load_stage = [&](int kk, int s) {
        const uint32_t st = sbase + s * STAGEB;
        #pragma unroll
        for (int i = 0; i < 16; i++) {
            const int idx = tid + i * 256;
            const int row = idx >> 3;          // 0..511
            const int c8  = idx & 7;
            const __half* src;
            if (row < 128)      src = Ah + (size_t)(bm + row) * DIM + kk * BK + c8 * 8;
            else if (row < 256) src = Al + (size_t)(bm + row - 128) * DIM + kk * BK + c8 * 8;
            else                src = B  + (size_t)(bn + row - 256) * DIM + kk * BK + c8 * 8;
            cp16(st + row * SA + c8 * 16, src);
        }
        CP_COMMIT();
    };

    load_stage(0, 0);
    load_stage(1, 1);

    const int lrow = lane & 15;
    const int lsel = (lane >> 4) * 16;    // 0 or 16 bytes

    for (int kk = 0; kk < NKK; kk++) {
        CP_WAIT1();
        __syncthreads();
        if (kk + 2 < NKK) load_stage(kk + 2, (kk + 2) % STAGES);
        else              CP_COMMIT();     // empty group keeps wait_group 1 sound

        const uint32_t st     = sbase + (kk % STAGES) * STAGEB;
        const uint32_t ahaddr = st + (m_base + lrow) * SA + lsel;
        const uint32_t aladdr = ahaddr + 128 * SA;
        const uint32_t baddr  = st + 256 * SA + (n_base + lrow) * SA + lsel;

        #pragma unroll
        for (int ks = 0; ks < 4; ks++) {
            uint32_t br[4][4];
            #pragma unroll
            for (int ni = 0; ni < 4; ni++) ldsm4(br[ni], baddr + ni * 16 * SA + ks * 32);

            uint32_t ar[4][4];
            #pragma unroll
            for (int mi = 0; mi < 4; mi++) ldsm4(ar[mi], ahaddr + mi * 16 * SA + ks * 32);
            #pragma unroll
            for (int mi = 0; mi < 4; mi++)
                #pragma unroll
                for (int nj = 0; nj < 8; nj++)
                    mma16816h(acc[mi][nj], ar[mi],
                              br[nj >> 1][nj & 1], br[nj >> 1][2 + (nj & 1)]);

            #pragma unroll
            for (int mi = 0; mi < 4; mi++) ldsm4(ar[mi], aladdr + mi * 16 * SA + ks * 32);
            #pragma unroll
            for (int mi = 0; mi < 4; mi++)
                #pragma unroll
                for (int nj = 0; nj < 8; nj++)
                    mma16816h(acc[mi][nj], ar[mi],
                              br[nj >> 1][nj & 1], br[nj >> 1][2 + (nj & 1)]);
        }
    }

    // epilogue
    const int g  = lane >> 2;
    const int t2 = (lane & 3) * 2;
    #pragma unroll
    for (int mi = 0; mi < 4; mi++) {
        const int row = bm + m_base + mi * 16 + g;
        OutT* crow = C + (size_t)row * ldc + bn + n_base + t2;
        #pragma unroll
        for (int nj = 0; nj < 8; nj++) {
            store2(crow + nj * 8,                   acc[mi][nj][0], acc[mi][nj][1]);
            store2(crow + (size_t)8 * ldc + nj * 8, acc[mi][nj][2], acc[mi][nj][3]);
        }
    }
}

// ---------------------------------------------------------------------------
// Per-token attention over HEADS axis; fp16 in, split-fp16 context out.
// ---------------------------------------------------------------------------
__global__ __launch_bounds__(128)
void attn_kernel(const __half* __restrict__ query,
                 const __half* __restrict__ kvproj,
                 __half* __restrict__ ctx_hi,
                 __half* __restrict__ ctx_lo) {
    const int t = blockIdx.x;
    const int tid = threadIdx.x;
    __shared__ float qs[DIM], ks[DIM], vs[DIM];
    __shared__ float w[HEADS * HEADS];
    __shared__ float sc[HEADS * HEADS];

    {
        const uint4* qp = (const uint4*)(query + (size_t)t * DIM);
        const uint4* kp = (const uint4*)(kvproj + (size_t)t * 2 * DIM);
        const uint4* vp = kp + DIM / 8;
        uint4 uq = qp[tid], uk = kp[tid], uv = vp[tid];
        const __half2* hq = (const __half2*)&uq;
        const __half2* hk = (const __half2*)&uk;
        const __half2* hv = (const __half2*)&uv;
        #pragma unroll
        for (int i = 0; i < 4; i++) {
            float2 f;
            f = __half22float2(hq[i]); qs[tid * 8 + 2 * i] = f.x; qs[tid * 8 + 2 * i + 1] = f.y;
            f = __half22float2(hk[i]); ks[tid * 8 + 2 * i] = f.x; ks[tid * 8 + 2 * i + 1] = f.y;
            f = __half22float2(hv[i]); vs[tid * 8 + 2 * i] = f.x; vs[tid * 8 + 2 * i + 1] = f.y;
        }
    }
    __syncthreads();

    if (tid < HEADS * HEADS) {
        const int h = tid >> 3, g = tid & 7;
        const float* qq = qs + h * DHEAD;
        const float* kk = ks + g * DHEAD;
        float s = 0.f;
        #pragma unroll 8
        for (int d = 0; d < DHEAD; d++) s += qq[d] * kk[d];
        sc[tid] = s * 0.08838834764831845f;   // 1/sqrt(128)
    }
    __syncthreads();

    if (tid < HEADS) {
        float m = -1e30f;
        #pragma unroll
        for (int g = 0; g < HEADS; g++) m = fmaxf(m, sc[tid * 8 + g]);
        float e[HEADS], sum = 0.f;
        #pragma unroll
        for (int g = 0; g < HEADS; g++) { e[g] = expf(sc[tid * 8 + g] - m); sum += e[g]; }
        const float inv = 1.0f / sum;
        #pragma unroll
        for (int g = 0; g < HEADS; g++) w[tid * 8 + g] = e[g] * inv;
    }
    __syncthreads();

    #pragma unroll
    for (int h = 0; h < HEADS; h++) {
        float a = 0.f;
        #pragma unroll
        for (int g = 0; g < HEADS; g++) a += w[h * 8 + g] * vs[g * DHEAD + tid];
        const size_t idx = (size_t)t * DIM + h * DHEAD + tid;
        __half hv = __float2half_rn(a);
        ctx_hi[idx] = hv;
        ctx_lo[idx] = __float2half_rn(a - __half2float(hv));
    }
}

// ---------------------------------------------------------------------------
// Host side.  Launch order: ln(0), wconv(1), gemm1(2), gemm2(3), attn(4),
// gemm3(5) -> ncu -s 5 captures gemm3.
// ---------------------------------------------------------------------------
extern "C" void kernel_launch(void* const* d_in, const int* in_sizes, int n_in,
                              void* d_out, int out_size) {
    const float* q       = (const float*)d_in[0];
    const float* kv      = (const float*)d_in[1];
    const float* gamma_m = (const float*)d_in[2];
    const float* beta_m  = (const float*)d_in[3];
    const float* gamma_l = (const float*)d_in[4];
    const float* beta_l  = (const float*)d_in[5];
    const float* Wq      = (const float*)d_in[6];
    const float* Wkv     = (const float*)d_in[7];
    const float* Wo      = (const float*)d_in[8];
    float* out = (float*)d_out;

    void *qn_hi, *qn_lo, *kvn_hi, *kvn_lo, *wq_h, *wkv_h, *wo_h;
    void *query, *kvproj, *ctx_hi, *ctx_lo;
    cudaGetSymbolAddress(&qn_hi,  g_qn_hi);   cudaGetSymbolAddress(&qn_lo,  g_qn_lo);
    cudaGetSymbolAddress(&kvn_hi, g_kvn_hi);  cudaGetSymbolAddress(&kvn_lo, g_kvn_lo);
    cudaGetSymbolAddress(&wq_h,   g_wq_h);    cudaGetSymbolAddress(&wkv_h,  g_wkv_h);
    cudaGetSymbolAddress(&wo_h,   g_wo_h);
    cudaGetSymbolAddress(&query,  g_query);   cudaGetSymbolAddress(&kvproj, g_kvproj);
    cudaGetSymbolAddress(&ctx_hi, g_ctx_hi);  cudaGetSymbolAddress(&ctx_lo, g_ctx_lo);

    cudaFuncSetAttribute(gemm_fp16_2term<__half>, cudaFuncAttributeMaxDynamicSharedMemorySize, SMEMB);
    cudaFuncSetAttribute(gemm_fp16_2term<float>,  cudaFuncAttributeMaxDynamicSharedMemorySize, SMEMB);

    // 0: fused LN + split for q and kv
    ln_split2_kernel<<<dim3(TOKENS, 2), 256>>>(q, kv, gamma_m, beta_m, gamma_l, beta_l,
                                               (__half*)qn_hi, (__half*)qn_lo,
                                               (__half*)kvn_hi, (__half*)kvn_lo);
    // 1: all weights -> fp16
    wconv_kernel<<<(4 * DIM * DIM) / 256, 256>>>(Wq, Wkv, Wo,
                                                 (__half*)wq_h, (__half*)wkv_h, (__half*)wo_h);

    // 2: query = qn @ Wq^T   [32768,1024] (fp16 out)
    gemm_fp16_2term<__half><<<dim3(DIM / BN, TOKENS / BM), 256, SMEMB>>>(
        (const __half*)qn_hi, (const __half*)qn_lo, (const __half*)wq_h,
        (__half*)query, DIM);
    // 3: kvproj = kvn @ Wkv^T  [32768,2048] (fp16 out)
    gemm_fp16_2term<__half><<<dim3(2 * DIM / BN, TOKENS / BM), 256, SMEMB>>>(
        (const __half*)kvn_hi, (const __half*)kvn_lo, (const __half*)wkv_h,
        (__half*)kvproj, 2 * DIM);

    // 4: attention
    attn_kernel<<<TOKENS, 128>>>((const __half*)query, (const __half*)kvproj,
                                 (__half*)ctx_hi, (__half*)ctx_lo);

    // 5: out = ctx @ Wo^T   [32768,1024] (fp32 out)  <- ncu target
    gemm_fp16_2term<float><<<dim3(DIM / BN, TOKENS / BM), 256, SMEMB>>>(
        (const __half*)ctx_hi, (const __half*)ctx_lo, (const __half*)wo_h,
        out, DIM);
}

// round 8
// speedup vs baseline: 2.3897x; 1.5277x over previous
#include <cuda_runtime.h>
#include <cuda_fp16.h>
#include <math.h>
#include <stdint.h>

// ---------------------------------------------------------------------------
// Problem constants
// ---------------------------------------------------------------------------
#define TOKENS   32768      // 16 * 2048
#define DIM      1024
#define HEADS    8
#define DHEAD    128
#define LN_EPS   1e-5f

// GEMM tiling: CTA 128x256, K-chunk 64, warp tile 64x64, 8 warps (2m x 4n)
#define BM       128
#define BN       256
#define BK       64
#define NKK      16           // 1024 / 64 K-chunks
#define STAGES   4
#define SA       144          // smem row stride (128B data + 16B pad)
#define ROWS_PER_STAGE (BM + BN)             // A(128) + B(256) = 384
#define STAGEB   (ROWS_PER_STAGE * SA)       // 55296
#define SMEMB    (STAGES * STAGEB)           // 221184

// ---------------------------------------------------------------------------
// Scratch (device globals; cudaMalloc forbidden)
// ---------------------------------------------------------------------------
__device__ __half g_qn  [TOKENS * DIM];
__device__ __half g_kvn [TOKENS * DIM];
__device__ __half g_wq_h [DIM * DIM];
__device__ __half g_wkv_h[2 * DIM * DIM];
__device__ __half g_wo_h [DIM * DIM];
__device__ __half g_query [TOKENS * DIM];
__device__ __half g_kvproj[TOKENS * 2 * DIM];
__device__ __half g_ctx   [TOKENS * DIM];

// ---------------------------------------------------------------------------
// PTX helpers (plain sm_80-level; harness PTX target is sm_103 non-'a')
// ---------------------------------------------------------------------------
__device__ __forceinline__ uint32_t smem_u32(const void* p) {
    uint32_t a;
    asm("{ .reg .u64 t; cvta.to.shared.u64 t, %1; cvt.u32.u64 %0, t; }" : "=r"(a) : "l"(p));
    return a;
}

__device__ __forceinline__ void cp16(uint32_t dst, const void* src) {
    asm volatile("cp.async.cg.shared.global [%0], [%1], 16;" :: "r"(dst), "l"(src));
}
#define CP_COMMIT() asm volatile("cp.async.commit_group;" ::: "memory")
#define CP_WAIT2()  asm volatile("cp.async.wait_group 2;" ::: "memory")

__device__ __forceinline__ void ldsm4(uint32_t* r, uint32_t addr) {
    asm volatile("ldmatrix.sync.aligned.m8n8.x4.shared.b16 {%0,%1,%2,%3}, [%4];"
                 : "=r"(r[0]), "=r"(r[1]), "=r"(r[2]), "=r"(r[3]) : "r"(addr));
}

__device__ __forceinline__ void mma16816h(float* d, const uint32_t* a, uint32_t b0, uint32_t b1) {
    asm volatile("mma.sync.aligned.m16n8k16.row.col.f32.f16.f16.f32 "
                 "{%0,%1,%2,%3}, {%4,%5,%6,%7}, {%8,%9}, {%0,%1,%2,%3};"
                 : "+f"(d[0]), "+f"(d[1]), "+f"(d[2]), "+f"(d[3])
                 : "r"(a[0]), "r"(a[1]), "r"(a[2]), "r"(a[3]), "r"(b0), "r"(b1));
}

// epilogue store: fp32 or fp16 output
__device__ __forceinline__ void store2(float* p, float a, float b)  { *(float2*)p  = make_float2(a, b); }
__device__ __forceinline__ void store2(__half* p, float a, float b) { *(__half2*)p = __floats2half2_rn(a, b); }

// ---------------------------------------------------------------------------
// Fused LayerNorm (both q and kv) -> fp16.  grid (TOKENS, 2).
// ---------------------------------------------------------------------------
__global__ __launch_bounds__(256)
void ln2_kernel(const float* __restrict__ q,  const float* __restrict__ kv,
                const float* __restrict__ gm, const float* __restrict__ bm,
                const float* __restrict__ gl, const float* __restrict__ bl,
                __half* __restrict__ qn, __half* __restrict__ kvn) {
    const int row = blockIdx.x;
    const int sel = blockIdx.y;
    const float* x     = sel ? kv : q;
    const float* gamma = sel ? gl : gm;
    const float* beta  = sel ? bl : bm;
    __half* y = sel ? kvn : qn;

    const int tid = threadIdx.x;
    float4 v = ((const float4*)(x + (size_t)row * DIM))[tid];

    float s  = v.x + v.y + v.z + v.w;
    float sq = v.x * v.x + v.y * v.y + v.z * v.z + v.w * v.w;
    #pragma unroll
    for (int o = 16; o > 0; o >>= 1) {
        s  += __shfl_xor_sync(0xffffffffu, s,  o);
        sq += __shfl_xor_sync(0xffffffffu, sq, o);
    }
    __shared__ float rs[8], rq[8];
    const int wid = tid >> 5, lane = tid & 31;
    if (lane == 0) { rs[wid] = s; rq[wid] = sq; }
    __syncthreads();
    float tot = 0.f, totq = 0.f;
    #pragma unroll
    for (int i = 0; i < 8; i++) { tot += rs[i]; totq += rq[i]; }

    const float mu   = tot * (1.0f / DIM);
    const float var  = totq * (1.0f / DIM) - mu * mu;
    const float rinv = rsqrtf(var + LN_EPS);

    float4 g = ((const float4*)gamma)[tid];
    float4 b = ((const float4*)beta)[tid];
    float o0 = (v.x - mu) * rinv * g.x + b.x;
    float o1 = (v.y - mu) * rinv * g.y + b.y;
    float o2 = (v.z - mu) * rinv * g.z + b.z;
    float o3 = (v.w - mu) * rinv * g.w + b.w;

    __half2* yp = (__half2*)(y + (size_t)row * DIM);
    yp[2 * tid]     = __floats2half2_rn(o0, o1);
    yp[2 * tid + 1] = __floats2half2_rn(o2, o3);
}

// ---------------------------------------------------------------------------
// All three weights -> fp16 in one launch
// ---------------------------------------------------------------------------
__global__ __launch_bounds__(256)
void wconv_kernel(const float* __restrict__ Wq, const float* __restrict__ Wkv,
                  const float* __restrict__ Wo,
                  __half* __restrict__ wq, __half* __restrict__ wkv, __half* __restrict__ wo) {
    const int i = blockIdx.x * 256 + threadIdx.x;    // 0 .. 4*DIM*DIM-1
    if (i < DIM * DIM)               wq[i]                 = __float2half_rn(Wq[i]);
    else if (i < 3 * DIM * DIM)      wkv[i - DIM * DIM]    = __float2half_rn(Wkv[i - DIM * DIM]);
    else                             wo[i - 3 * DIM * DIM] = __float2half_rn(Wo[i - 3 * DIM * DIM]);
}

// ---------------------------------------------------------------------------
// fp16 GEMM:  C[M,N] = A[M,K] * B[N,K]^T, fp32 accum.
// CTA 128x256, 8 warps of 64x64, 4-stage cp.async pipeline (3-deep prefetch).
// Stage layout: [A 128 rows][B 256 rows], row = 128B data + 16B pad.
// ---------------------------------------------------------------------------
template <typename OutT>
__global__ __launch_bounds__(256, 1)
void gemm_fp16(const __half* __restrict__ A, const __half* __restrict__ B,
               OutT* __restrict__ C, int ldc) {
    extern __shared__ char smem[];
    const uint32_t sbase = smem_u32(smem);
    const int tid  = threadIdx.x;
    const int wid  = tid >> 5;
    const int lane = tid & 31;
    const int bm = blockIdx.y * BM;
    const int bn = blockIdx.x * BN;
    const int m_base = (wid >> 2) * 64;   // 0 or 64
    const int n_base = (wid & 3) * 64;    // 0,64,128,192

    float acc[4][8][4];
    #pragma unroll
    for (int i = 0; i < 4; i++)
        #pragma unroll
        for (int j = 0; j < 8; j++)
            #pragma unroll
            for (int k = 0; k < 4; k++) acc[i][j][k] = 0.f;

    // stage loader: 384 rows x 128B, 16B per cp.async, 12 per thread
    auto load_stage = [&](int kk, int s) {
        const uint32_t st = sbase + s * STAGEB;
        #pragma unroll
        for (int i = 0; i < 12; i++) {
            const int idx = tid + i * 256;
            const int row = idx >> 3;          // 0..383
            const int c8  = idx & 7;
            const __half* src = (row < 128)
                ? A + (size_t)(bm + row) * DIM + kk * BK + c8 * 8
                : B + (size_t)(bn + row - 128) * DIM + kk * BK + c8 * 8;
            cp16(st + row * SA + c8 * 16, src);
        }
        CP_COMMIT();
    };

    load_stage(0, 0);
    load_stage(1, 1);
    load_stage(2, 2);

    const int lrow = lane & 15;
    const int lsel = (lane >> 4) * 16;    // 0 or 16 bytes

    for (int kk = 0; kk < NKK; kk++) {
        CP_WAIT2();                        // stage kk resident (<=2 groups pending)
        __syncthreads();
        if (kk + 3 < NKK) load_stage(kk + 3, (kk + 3) % STAGES);
        else              CP_COMMIT();     // empty group keeps wait_group 2 sound

        const uint32_t st    = sbase + (kk % STAGES) * STAGEB;
        const uint32_t aaddr = st + (m_base + lrow) * SA + lsel;
        const uint32_t baddr = st + 128 * SA + (n_base + lrow) * SA + lsel;

        #pragma unroll
        for (int ks = 0; ks < 4; ks++) {
            uint32_t br[4][4];
            #pragma unroll
            for (int ni = 0; ni < 4; ni++) ldsm4(br[ni], baddr + ni * 16 * SA + ks * 32);

            uint32_t ar[4][4];
            #pragma unroll
            for (int mi = 0; mi < 4; mi++) ldsm4(ar[mi], aaddr + mi * 16 * SA + ks * 32);

            #pragma unroll
            for (int mi = 0; mi < 4; mi++)
                #pragma unroll
                for (int nj = 0; nj < 8; nj++)
                    mma16816h(acc[mi][nj], ar[mi],
                              br[nj >> 1][nj & 1], br[nj >> 1][2 + (nj & 1)]);
        }
    }

    // epilogue
    const int g  = lane >> 2;
    const int t2 = (lane & 3) * 2;
    #pragma unroll
    for (int mi = 0; mi < 4; mi++) {
        const int row = bm + m_base + mi * 16 + g;
        OutT* crow = C + (size_t)row * ldc + bn + n_base + t2;
        #pragma unroll
        for (int nj = 0; nj < 8; nj++) {
            store2(crow + nj * 8,                   acc[mi][nj][0], acc[mi][nj][1]);
            store2(crow + (size_t)8 * ldc + nj * 8, acc[mi][nj][2], acc[mi][nj][3]);
        }
    }
}

// ---------------------------------------------------------------------------
// Per-token attention over HEADS axis; fp16 in, fp16 context out.
// ---------------------------------------------------------------------------
__global__ __launch_bounds__(128)
void attn_kernel(const __half* __restrict__ query,
                 const __half* __restrict__ kvproj,
                 __half* __restrict__ ctx) {
    const int t = blockIdx.x;
    const int tid = threadIdx.x;
    __shared__ float qs[DIM], ks[DIM], vs[DIM];
    __shared__ float w[HEADS * HEADS];
    __shared__ float sc[HEADS * HEADS];

    {
        const uint4* qp = (const uint4*)(query + (size_t)t * DIM);
        const uint4* kp = (const uint4*)(kvproj + (size_t)t * 2 * DIM);
        const uint4* vp = kp + DIM / 8;
        uint4 uq = qp[tid], uk = kp[tid], uv = vp[tid];
        const __half2* hq = (const __half2*)&uq;
        const __half2* hk = (const __half2*)&uk;
        const __half2* hv = (const __half2*)&uv;
        #pragma unroll
        for (int i = 0; i < 4; i++) {
            float2 f;
            f = __half22float2(hq[i]); qs[tid * 8 + 2 * i] = f.x; qs[tid * 8 + 2 * i + 1] = f.y;
            f = __half22float2(hk[i]); ks[tid * 8 + 2 * i] = f.x; ks[tid * 8 + 2 * i + 1] = f.y;
            f = __half22float2(hv[i]); vs[tid * 8 + 2 * i] = f.x; vs[tid * 8 + 2 * i + 1] = f.y;
        }
    }
    __syncthreads();

    if (tid < HEADS * HEADS) {
        const int h = tid >> 3, g = tid & 7;
        const float* qq = qs + h * DHEAD;
        const float* kk = ks + g * DHEAD;
        float s = 0.f;
        #pragma unroll 8
        for (int d = 0; d < DHEAD; d++) s += qq[d] * kk[d];
        sc[tid] = s * 0.08838834764831845f;   // 1/sqrt(128)
    }
    __syncthreads();

    if (tid < HEADS) {
        float m = -1e30f;
        #pragma unroll
        for (int g = 0; g < HEADS; g++) m = fmaxf(m, sc[tid * 8 + g]);
        float e[HEADS], sum = 0.f;
        #pragma unroll
        for (int g = 0; g < HEADS; g++) { e[g] = expf(sc[tid * 8 + g] - m); sum += e[g]; }
        const float inv = 1.0f / sum;
        #pragma unroll
        for (int g = 0; g < HEADS; g++) w[tid * 8 + g] = e[g] * inv;
    }
    __syncthreads();

    #pragma unroll
    for (int h = 0; h < HEADS; h++) {
        float a = 0.f;
        #pragma unroll
        for (int g = 0; g < HEADS; g++) a += w[h * 8 + g] * vs[g * DHEAD + tid];
        ctx[(size_t)t * DIM + h * DHEAD + tid] = __float2half_rn(a);
    }
}

// ---------------------------------------------------------------------------
// Host side.  Launch order: ln(0), wconv(1), gemm1(2), gemm2(3), attn(4),
// gemm3(5) -> ncu -s 5 captures gemm3.
// ---------------------------------------------------------------------------
extern "C" void kernel_launch(void* const* d_in, const int* in_sizes, int n_in,
                              void* d_out, int out_size) {
    const float* q       = (const float*)d_in[0];
    const float* kv      = (const float*)d_in[1];
    const float* gamma_m = (const float*)d_in[2];
    const float* beta_m  = (const float*)d_in[3];
    const float* gamma_l = (const float*)d_in[4];
    const float* beta_l  = (const float*)d_in[5];
    const float* Wq      = (const float*)d_in[6];
    const float* Wkv     = (const float*)d_in[7];
    const float* Wo      = (const float*)d_in[8];
    float* out = (float*)d_out;

    void *qn, *kvn, *wq_h, *wkv_h, *wo_h, *query, *kvproj, *ctx;
    cudaGetSymbolAddress(&qn,    g_qn);     cudaGetSymbolAddress(&kvn,   g_kvn);
    cudaGetSymbolAddress(&wq_h,  g_wq_h);   cudaGetSymbolAddress(&wkv_h, g_wkv_h);
    cudaGetSymbolAddress(&wo_h,  g_wo_h);
    cudaGetSymbolAddress(&query, g_query);  cudaGetSymbolAddress(&kvproj, g_kvproj);
    cudaGetSymbolAddress(&ctx,   g_ctx);

    cudaFuncSetAttribute(gemm_fp16<__half>, cudaFuncAttributeMaxDynamicSharedMemorySize, SMEMB);
    cudaFuncSetAttribute(gemm_fp16<float>,  cudaFuncAttributeMaxDynamicSharedMemorySize, SMEMB);

    // 0: fused LN for q and kv -> fp16
    ln2_kernel<<<dim3(TOKENS, 2), 256>>>(q, kv, gamma_m, beta_m, gamma_l, beta_l,
                                         (__half*)qn, (__half*)kvn);
    // 1: all weights -> fp16
    wconv_kernel<<<(4 * DIM * DIM) / 256, 256>>>(Wq, Wkv, Wo,
                                                 (__half*)wq_h, (__half*)wkv_h, (__half*)wo_h);

    // 2: query = qn @ Wq^T   [32768,1024] (fp16 out)
    gemm_fp16<__half><<<dim3(DIM / BN, TOKENS / BM), 256, SMEMB>>>(
        (const __half*)qn, (const __half*)wq_h, (__half*)query, DIM);
    // 3: kvproj = kvn @ Wkv^T  [32768,2048] (fp16 out)
    gemm_fp16<__half><<<dim3(2 * DIM / BN, TOKENS / BM), 256, SMEMB>>>(
        (const __half*)kvn, (const __half*)wkv_h, (__half*)kvproj, 2 * DIM);

    // 4: attention
    attn_kernel<<<TOKENS, 128>>>((const __half*)query, (const __half*)kvproj, (__half*)ctx);

    // 5: out = ctx @ Wo^T   [32768,1024] (fp32 out)  <- ncu target
    gemm_fp16<float><<<dim3(DIM / BN, TOKENS / BM), 256, SMEMB>>>(
        (const __half*)ctx, (const __half*)wo_h, out, DIM);
}

// round 9
// speedup vs baseline: 2.4620x; 1.0303x over previous
#include <cuda_runtime.h>
#include <cuda_fp16.h>
#include <math.h>
#include <stdint.h>

// ---------------------------------------------------------------------------
// Problem constants
// ---------------------------------------------------------------------------
#define TOKENS   32768      // 16 * 2048
#define DIM      1024
#define HEADS    8
#define DHEAD    128
#define LN_EPS   1e-5f

// GEMM tiling: CTA 128x128, K-chunk 64, warp tile 64x32, 8 warps (2m x 4n)
// 2 CTAs per SM -> barrier stalls of one CTA covered by the other.
#define BM       128
#define BN       128
#define BK       64
#define NKK      16           // 1024 / 64 K-chunks
#define STAGES   3
#define SA       144          // smem row stride (128B data + 16B pad)
#define ROWS_PER_STAGE (BM + BN)             // A(128) + B(128) = 256
#define STAGEB   (ROWS_PER_STAGE * SA)       // 36864
#define SMEMB    (STAGES * STAGEB)           // 110592 (x2 CTAs = 216KB/SM)

// ---------------------------------------------------------------------------
// Scratch (device globals; cudaMalloc forbidden)
// ---------------------------------------------------------------------------
__device__ __half g_qn  [TOKENS * DIM];
__device__ __half g_kvn [TOKENS * DIM];
__device__ __half g_wq_h [DIM * DIM];
__device__ __half g_wkv_h[2 * DIM * DIM];
__device__ __half g_wo_h [DIM * DIM];
__device__ __half g_query [TOKENS * DIM];
__device__ __half g_kvproj[TOKENS * 2 * DIM];
__device__ __half g_ctx   [TOKENS * DIM];

// ---------------------------------------------------------------------------
// PTX helpers (plain sm_80-level; harness PTX target is sm_103 non-'a')
// ---------------------------------------------------------------------------
__device__ __forceinline__ uint32_t smem_u32(const void* p) {
    uint32_t a;
    asm("{ .reg .u64 t; cvta.to.shared.u64 t, %1; cvt.u32.u64 %0, t; }" : "=r"(a) : "l"(p));
    return a;
}

__device__ __forceinline__ void cp16(uint32_t dst, const void* src) {
    asm volatile("cp.async.cg.shared.global [%0], [%1], 16;" :: "r"(dst), "l"(src));
}
#define CP_COMMIT() asm volatile("cp.async.commit_group;" ::: "memory")
#define CP_WAIT1()  asm volatile("cp.async.wait_group 1;" ::: "memory")

__device__ __forceinline__ void ldsm4(uint32_t* r, uint32_t addr) {
    asm volatile("ldmatrix.sync.aligned.m8n8.x4.shared.b16 {%0,%1,%2,%3}, [%4];"
                 : "=r"(r[0]), "=r"(r[1]), "=r"(r[2]), "=r"(r[3]) : "r"(addr));
}

__device__ __forceinline__ void mma16816h(float* d, const uint32_t* a, uint32_t b0, uint32_t b1) {
    asm volatile("mma.sync.aligned.m16n8k16.row.col.f32.f16.f16.f32 "
                 "{%0,%1,%2,%3}, {%4,%5,%6,%7}, {%8,%9}, {%0,%1,%2,%3};"
                 : "+f"(d[0]), "+f"(d[1]), "+f"(d[2]), "+f"(d[3])
                 : "r"(a[0]), "r"(a[1]), "r"(a[2]), "r"(a[3]), "r"(b0), "r"(b1));
}

// epilogue store: fp32 or fp16 output
__device__ __forceinline__ void store2(float* p, float a, float b)  { *(float2*)p  = make_float2(a, b); }
__device__ __forceinline__ void store2(__half* p, float a, float b) { *(__half2*)p = __floats2half2_rn(a, b); }

// ---------------------------------------------------------------------------
// Fused LayerNorm (both q and kv) -> fp16.  grid (TOKENS, 2).
// ---------------------------------------------------------------------------
__global__ __launch_bounds__(256)
void ln2_kernel(const float* __restrict__ q,  const float* __restrict__ kv,
                const float* __restrict__ gm, const float* __restrict__ bm,
                const float* __restrict__ gl, const float* __restrict__ bl,
                __half* __restrict__ qn, __half* __restrict__ kvn) {
    const int row = blockIdx.x;
    const int sel = blockIdx.y;
    const float* x     = sel ? kv : q;
    const float* gamma = sel ? gl : gm;
    const float* beta  = sel ? bl : bm;
    __half* y = sel ? kvn : qn;

    const int tid = threadIdx.x;
    float4 v = ((const float4*)(x + (size_t)row * DIM))[tid];

    float s  = v.x + v.y + v.z + v.w;
    float sq = v.x * v.x + v.y * v.y + v.z * v.z + v.w * v.w;
    #pragma unroll
    for (int o = 16; o > 0; o >>= 1) {
        s  += __shfl_xor_sync(0xffffffffu, s,  o);
        sq += __shfl_xor_sync(0xffffffffu, sq, o);
    }
    __shared__ float rs[8], rq[8];
    const int wid = tid >> 5, lane = tid & 31;
    if (lane == 0) { rs[wid] = s; rq[wid] = sq; }
    __syncthreads();
    float tot = 0.f, totq = 0.f;
    #pragma unroll
    for (int i = 0; i < 8; i++) { tot += rs[i]; totq += rq[i]; }

    const float mu   = tot * (1.0f / DIM);
    const float var  = totq * (1.0f / DIM) - mu * mu;
    const float rinv = rsqrtf(var + LN_EPS);

    float4 g = ((const float4*)gamma)[tid];
    float4 b = ((const float4*)beta)[tid];
    float o0 = (v.x - mu) * rinv * g.x + b.x;
    float o1 = (v.y - mu) * rinv * g.y + b.y;
    float o2 = (v.z - mu) * rinv * g.z + b.z;
    float o3 = (v.w - mu) * rinv * g.w + b.w;

    __half2* yp = (__half2*)(y + (size_t)row * DIM);
    yp[2 * tid]     = __floats2half2_rn(o0, o1);
    yp[2 * tid + 1] = __floats2half2_rn(o2, o3);
}

// ---------------------------------------------------------------------------
// All three weights -> fp16 in one launch
// ---------------------------------------------------------------------------
__global__ __launch_bounds__(256)
void wconv_kernel(const float* __restrict__ Wq, const float* __restrict__ Wkv,
                  const float* __restrict__ Wo,
                  __half* __restrict__ wq, __half* __restrict__ wkv, __half* __restrict__ wo) {
    const int i = blockIdx.x * 256 + threadIdx.x;    // 0 .. 4*DIM*DIM-1
    if (i < DIM * DIM)               wq[i]                 = __float2half_rn(Wq[i]);
    else if (i < 3 * DIM * DIM)      wkv[i - DIM * DIM]    = __float2half_rn(Wkv[i - DIM * DIM]);
    else                             wo[i - 3 * DIM * DIM] = __float2half_rn(Wo[i - 3 * DIM * DIM]);
}

// ---------------------------------------------------------------------------
// fp16 GEMM:  C[M,N] = A[M,K] * B[N,K]^T, fp32 accum.
// CTA 128x128, 8 warps of 64x32, 3-stage cp.async pipeline, 2 CTAs/SM.
// Stage layout: [A 128 rows][B 128 rows], row = 128B data + 16B pad.
// ---------------------------------------------------------------------------
template <typename OutT>
__global__ __launch_bounds__(256, 2)
void gemm_fp16(const __half* __restrict__ A, const __half* __restrict__ B,
               OutT* __restrict__ C, int ldc) {
    extern __shared__ char smem[];
    const uint32_t sbase = smem_u32(smem);
    const int tid  = threadIdx.x;
    const int wid  = tid >> 5;
    const int lane = tid & 31;
    const int bm = blockIdx.y * BM;
    const int bn = blockIdx.x * BN;
    const int m_base = (wid >> 2) * 64;   // 0 or 64
    const int n_base = (wid & 3) * 32;    // 0,32,64,96

    float acc[4][4][4];
    #pragma unroll
    for (int i = 0; i < 4; i++)
        #pragma unroll
        for (int j = 0; j < 4; j++)
            #pragma unroll
            for (int k = 0; k < 4; k++) acc[i][j][k] = 0.f;

    // stage loader: 256 rows x 128B, 16B per cp.async, 8 per thread
    auto load_stage = [&](int kk, int s) {
        const uint32_t st = sbase + s * STAGEB;
        #pragma unroll
        for (int i = 0; i < 8; i++) {
            const int idx = tid + i * 256;
            const int row = idx >> 3;          // 0..255
            const int c8  = idx & 7;
            const __half* src = (row < 128)
                ? A + (size_t)(bm + row) * DIM + kk * BK + c8 * 8
                : B + (size_t)(bn + row - 128) * DIM + kk * BK + c8 * 8;
            cp16(st + row * SA + c8 * 16, src);
        }
        CP_COMMIT();
    };

    load_stage(0, 0);
    load_stage(1, 1);

    const int lrow = lane & 15;
    const int lsel = (lane >> 4) * 16;    // 0 or 16 bytes

    for (int kk = 0; kk < NKK; kk++) {
        CP_WAIT1();
        __syncthreads();
        if (kk + 2 < NKK) load_stage(kk + 2, (kk + 2) % STAGES);
        else              CP_COMMIT();     // empty group keeps wait_group 1 sound

        const uint32_t st    = sbase + (kk % STAGES) * STAGEB;
        const uint32_t aaddr = st + (m_base + lrow) * SA + lsel;
        const uint32_t baddr = st + 128 * SA + (n_base + lrow) * SA + lsel;

        #pragma unroll
        for (int ks = 0; ks < 4; ks++) {
            uint32_t br[2][4];
            #pragma unroll
            for (int ni = 0; ni < 2; ni++) ldsm4(br[ni], baddr + ni * 16 * SA + ks * 32);

            uint32_t ar[4][4];
            #pragma unroll
            for (int mi = 0; mi < 4; mi++) ldsm4(ar[mi], aaddr + mi * 16 * SA + ks * 32);

            #pragma unroll
            for (int mi = 0; mi < 4; mi++)
                #pragma unroll
                for (int nj = 0; nj < 4; nj++)
                    mma16816h(acc[mi][nj], ar[mi],
                              br[nj >> 1][nj & 1], br[nj >> 1][2 + (nj & 1)]);
        }
    }

    // epilogue
    const int g  = lane >> 2;
    const int t2 = (lane & 3) * 2;
    #pragma unroll
    for (int mi = 0; mi < 4; mi++) {
        const int row = bm + m_base + mi * 16 + g;
        OutT* crow = C + (size_t)row * ldc + bn + n_base + t2;
        #pragma unroll
        for (int nj = 0; nj < 4; nj++) {
            store2(crow + nj * 8,                   acc[mi][nj][0], acc[mi][nj][1]);
            store2(crow + (size_t)8 * ldc + nj * 8, acc[mi][nj][2], acc[mi][nj][3]);
        }
    }
}

// ---------------------------------------------------------------------------
// Per-token attention over HEADS axis; fp16 in, fp16 context out.
// ---------------------------------------------------------------------------
__global__ __launch_bounds__(128)
void attn_kernel(const __half* __restrict__ query,
                 const __half* __restrict__ kvproj,
                 __half* __restrict__ ctx) {
    const int t = blockIdx.x;
    const int tid = threadIdx.x;
    __shared__ float qs[DIM], ks[DIM], vs[DIM];
    __shared__ float w[HEADS * HEADS];
    __shared__ float sc[HEADS * HEADS];

    {
        const uint4* qp = (const uint4*)(query + (size_t)t * DIM);
        const uint4* kp = (const uint4*)(kvproj + (size_t)t * 2 * DIM);
        const uint4* vp = kp + DIM / 8;
        uint4 uq = qp[tid], uk = kp[tid], uv = vp[tid];
        const __half2* hq = (const __half2*)&uq;
        const __half2* hk = (const __half2*)&uk;
        const __half2* hv = (const __half2*)&uv;
        #pragma unroll
        for (int i = 0; i < 4; i++) {
            float2 f;
            f = __half22float2(hq[i]); qs[tid * 8 + 2 * i] = f.x; qs[tid * 8 + 2 * i + 1] = f.y;
            f = __half22float2(hk[i]); ks[tid * 8 + 2 * i] = f.x; ks[tid * 8 + 2 * i + 1] = f.y;
            f = __half22float2(hv[i]); vs[tid * 8 + 2 * i] = f.x; vs[tid * 8 + 2 * i + 1] = f.y;
        }
    }
    __syncthreads();

    if (tid < HEADS * HEADS) {
        const int h = tid >> 3, g = tid & 7;
        const float* qq = qs + h * DHEAD;
        const float* kk = ks + g * DHEAD;
        float s = 0.f;
        #pragma unroll 8
        for (int d = 0; d < DHEAD; d++) s += qq[d] * kk[d];
        sc[tid] = s * 0.08838834764831845f;   // 1/sqrt(128)
    }
    __syncthreads();

    if (tid < HEADS) {
        float m = -1e30f;
        #pragma unroll
        for (int g = 0; g < HEADS; g++) m = fmaxf(m, sc[tid * 8 + g]);
        float e[HEADS], sum = 0.f;
        #pragma unroll
        for (int g = 0; g < HEADS; g++) { e[g] = expf(sc[tid * 8 + g] - m); sum += e[g]; }
        const float inv = 1.0f / sum;
        #pragma unroll
        for (int g = 0; g < HEADS; g++) w[tid * 8 + g] = e[g] * inv;
    }
    __syncthreads();

    #pragma unroll
    for (int h = 0; h < HEADS; h++) {
        float a = 0.f;
        #pragma unroll
        for (int g = 0; g < HEADS; g++) a += w[h * 8 + g] * vs[g * DHEAD + tid];
        ctx[(size_t)t * DIM + h * DHEAD + tid] = __float2half_rn(a);
    }
}

// ---------------------------------------------------------------------------
// Host side.  Launch order: ln(0), wconv(1), gemm1(2), gemm2(3), attn(4),
// gemm3(5) -> ncu -s 5 captures gemm3.
// ---------------------------------------------------------------------------
extern "C" void kernel_launch(void* const* d_in, const int* in_sizes, int n_in,
                              void* d_out, int out_size) {
    const float* q       = (const float*)d_in[0];
    const float* kv      = (const float*)d_in[1];
    const float* gamma_m = (const float*)d_in[2];
    const float* beta_m  = (const float*)d_in[3];
    const float* gamma_l = (const float*)d_in[4];
    const float* beta_l  = (const float*)d_in[5];
    const float* Wq      = (const float*)d_in[6];
    const float* Wkv     = (const float*)d_in[7];
    const float* Wo      = (const float*)d_in[8];
    float* out = (float*)d_out;

    void *qn, *kvn, *wq_h, *wkv_h, *wo_h, *query, *kvproj, *ctx;
    cudaGetSymbolAddress(&qn,    g_qn);     cudaGetSymbolAddress(&kvn,   g_kvn);
    cudaGetSymbolAddress(&wq_h,  g_wq_h);   cudaGetSymbolAddress(&wkv_h, g_wkv_h);
    cudaGetSymbolAddress(&wo_h,  g_wo_h);
    cudaGetSymbolAddress(&query, g_query);  cudaGetSymbolAddress(&kvproj, g_kvproj);
    cudaGetSymbolAddress(&ctx,   g_ctx);

    cudaFuncSetAttribute(gemm_fp16<__half>, cudaFuncAttributeMaxDynamicSharedMemorySize, SMEMB);
    cudaFuncSetAttribute(gemm_fp16<float>,  cudaFuncAttributeMaxDynamicSharedMemorySize, SMEMB);

    // 0: fused LN for q and kv -> fp16
    ln2_kernel<<<dim3(TOKENS, 2), 256>>>(q, kv, gamma_m, beta_m, gamma_l, beta_l,
                                         (__half*)qn, (__half*)kvn);
    // 1: all weights -> fp16
    wconv_kernel<<<(4 * DIM * DIM) / 256, 256>>>(Wq, Wkv, Wo,
                                                 (__half*)wq_h, (__half*)wkv_h, (__half*)wo_h);

    // 2: query = qn @ Wq^T   [32768,1024] (fp16 out)
    gemm_fp16<__half><<<dim3(DIM / BN, TOKENS / BM), 256, SMEMB>>>(
        (const __half*)qn, (const __half*)wq_h, (__half*)query, DIM);
    // 3: kvproj = kvn @ Wkv^T  [32768,2048] (fp16 out)
    gemm_fp16<__half><<<dim3(2 * DIM / BN, TOKENS / BM), 256, SMEMB>>>(
        (const __half*)kvn, (const __half*)wkv_h, (__half*)kvproj, 2 * DIM);

    // 4: attention
    attn_kernel<<<TOKENS, 128>>>((const __half*)query, (const __half*)kvproj, (__half*)ctx);

    // 5: out = ctx @ Wo^T   [32768,1024] (fp32 out)  <- ncu target
    gemm_fp16<float><<<dim3(DIM / BN, TOKENS / BM), 256, SMEMB>>>(
        (const __half*)ctx, (const __half*)wo_h, out, DIM);
}

// round 10
// speedup vs baseline: 3.0616x; 1.2436x over previous
#include <cuda_runtime.h>
#include <cuda_fp16.h>
#include <math.h>
#include <stdint.h>

// ---------------------------------------------------------------------------
// Problem constants
// ---------------------------------------------------------------------------
#define TOKENS   32768      // 16 * 2048
#define DIM      1024
#define HEADS    8
#define DHEAD    128
#define LN_EPS   1e-5f

// GEMM tiling: CTA 128x128, K-chunk 64, warp tile 64x32, 8 warps (2m x 4n)
#define BM       128
#define BN       128
#define BK       64
#define NKK      16           // 1024 / 64 K-chunks
#define STAGES   3
#define SA       144          // smem row stride (128B data + 16B pad)
#define ROWS_PER_STAGE (BM + BN)             // A(128) + B(128) = 256
#define STAGEB   (ROWS_PER_STAGE * SA)       // 36864
#define SMEMB    (STAGES * STAGEB)           // 110592 (x2 CTAs = 216KB/SM)

// Attention: 8 tokens per 256-thread block, one warp per token.
#define ATOK     8
#define AROWS    136                          // padded row stride in halves
#define AWBYTES  (3 * 8 * AROWS * 2 + 256)    // q,k,v (6528B) + sc/w (256B)
#define AWSTRIDE 6912                         // 16B-aligned per-warp region
#define ASMEM    (ATOK * AWSTRIDE)            // 55296

// ---------------------------------------------------------------------------
// Scratch (device globals; cudaMalloc forbidden)
// ---------------------------------------------------------------------------
__device__ __half g_qn  [TOKENS * DIM];
__device__ __half g_kvn [TOKENS * DIM];
__device__ __half g_wq_h [DIM * DIM];
__device__ __half g_wkv_h[2 * DIM * DIM];
__device__ __half g_wo_h [DIM * DIM];
__device__ __half g_query [TOKENS * DIM];
__device__ __half g_kvproj[TOKENS * 2 * DIM];
__device__ __half g_ctx   [TOKENS * DIM];

// ---------------------------------------------------------------------------
// PTX helpers (plain sm_80-level; harness PTX target is sm_103 non-'a')
// ---------------------------------------------------------------------------
__device__ __forceinline__ uint32_t smem_u32(const void* p) {
    uint32_t a;
    asm("{ .reg .u64 t; cvta.to.shared.u64 t, %1; cvt.u32.u64 %0, t; }" : "=r"(a) : "l"(p));
    return a;
}

__device__ __forceinline__ void cp16(uint32_t dst, const void* src) {
    asm volatile("cp.async.cg.shared.global [%0], [%1], 16;" :: "r"(dst), "l"(src));
}
#define CP_COMMIT() asm volatile("cp.async.commit_group;" ::: "memory")
#define CP_WAIT1()  asm volatile("cp.async.wait_group 1;" ::: "memory")

__device__ __forceinline__ void ldsm4(uint32_t* r, uint32_t addr) {
    asm volatile("ldmatrix.sync.aligned.m8n8.x4.shared.b16 {%0,%1,%2,%3}, [%4];"
                 : "=r"(r[0]), "=r"(r[1]), "=r"(r[2]), "=r"(r[3]) : "r"(addr));
}

__device__ __forceinline__ void mma16816h(float* d, const uint32_t* a, uint32_t b0, uint32_t b1) {
    asm volatile("mma.sync.aligned.m16n8k16.row.col.f32.f16.f16.f32 "
                 "{%0,%1,%2,%3}, {%4,%5,%6,%7}, {%8,%9}, {%0,%1,%2,%3};"
                 : "+f"(d[0]), "+f"(d[1]), "+f"(d[2]), "+f"(d[3])
                 : "r"(a[0]), "r"(a[1]), "r"(a[2]), "r"(a[3]), "r"(b0), "r"(b1));
}

// epilogue store: fp32 or fp16 output
__device__ __forceinline__ void store2(float* p, float a, float b)  { *(float2*)p  = make_float2(a, b); }
__device__ __forceinline__ void store2(__half* p, float a, float b) { *(__half2*)p = __floats2half2_rn(a, b); }

// ---------------------------------------------------------------------------
// Fused LayerNorm (both q and kv) -> fp16.  grid (TOKENS, 2).
// ---------------------------------------------------------------------------
__global__ __launch_bounds__(256)
void ln2_kernel(const float* __restrict__ q,  const float* __restrict__ kv,
                const float* __restrict__ gm, const float* __restrict__ bm,
                const float* __restrict__ gl, const float* __restrict__ bl,
                __half* __restrict__ qn, __half* __restrict__ kvn) {
    const int row = blockIdx.x;
    const int sel = blockIdx.y;
    const float* x     = sel ? kv : q;
    const float* gamma = sel ? gl : gm;
    const float* beta  = sel ? bl : bm;
    __half* y = sel ? kvn : qn;

    const int tid = threadIdx.x;
    float4 v = ((const float4*)(x + (size_t)row * DIM))[tid];

    float s  = v.x + v.y + v.z + v.w;
    float sq = v.x * v.x + v.y * v.y + v.z * v.z + v.w * v.w;
    #pragma unroll
    for (int o = 16; o > 0; o >>= 1) {
        s  += __shfl_xor_sync(0xffffffffu, s,  o);
        sq += __shfl_xor_sync(0xffffffffu, sq, o);
    }
    __shared__ float rs[8], rq[8];
    const int wid = tid >> 5, lane = tid & 31;
    if (lane == 0) { rs[wid] = s; rq[wid] = sq; }
    __syncthreads();
    float tot = 0.f, totq = 0.f;
    #pragma unroll
    for (int i = 0; i < 8; i++) { tot += rs[i]; totq += rq[i]; }

    const float mu   = tot * (1.0f / DIM);
    const float var  = totq * (1.0f / DIM) - mu * mu;
    const float rinv = rsqrtf(var + LN_EPS);

    float4 g = ((const float4*)gamma)[tid];
    float4 b = ((const float4*)beta)[tid];
    float o0 = (v.x - mu) * rinv * g.x + b.x;
    float o1 = (v.y - mu) * rinv * g.y + b.y;
    float o2 = (v.z - mu) * rinv * g.z + b.z;
    float o3 = (v.w - mu) * rinv * g.w + b.w;

    __half2* yp = (__half2*)(y + (size_t)row * DIM);
    yp[2 * tid]     = __floats2half2_rn(o0, o1);
    yp[2 * tid + 1] = __floats2half2_rn(o2, o3);
}

// ---------------------------------------------------------------------------
// All three weights -> fp16 in one launch
// ---------------------------------------------------------------------------
__global__ __launch_bounds__(256)
void wconv_kernel(const float* __restrict__ Wq, const float* __restrict__ Wkv,
                  const float* __restrict__ Wo,
                  __half* __restrict__ wq, __half* __restrict__ wkv, __half* __restrict__ wo) {
    const int i = blockIdx.x * 256 + threadIdx.x;    // 0 .. 4*DIM*DIM-1
    if (i < DIM * DIM)               wq[i]                 = __float2half_rn(Wq[i]);
    else if (i < 3 * DIM * DIM)      wkv[i - DIM * DIM]    = __float2half_rn(Wkv[i - DIM * DIM]);
    else                             wo[i - 3 * DIM * DIM] = __float2half_rn(Wo[i - 3 * DIM * DIM]);
}

// ---------------------------------------------------------------------------
// fp16 GEMM:  C[M,N] = A[M,K] * B[N,K]^T, fp32 accum.
// CTA 128x128, 8 warps of 64x32, 3-stage cp.async pipeline, 2 CTAs/SM.
// (unchanged from round 9)
// ---------------------------------------------------------------------------
template <typename OutT>
__global__ __launch_bounds__(256, 2)
void gemm_fp16(const __half* __restrict__ A, const __half* __restrict__ B,
               OutT* __restrict__ C, int ldc) {
    extern __shared__ char smem[];
    const uint32_t sbase = smem_u32(smem);
    const int tid  = threadIdx.x;
    const int wid  = tid >> 5;
    const int lane = tid & 31;
    const int bm = blockIdx.y * BM;
    const int bn = blockIdx.x * BN;
    const int m_base = (wid >> 2) * 64;   // 0 or 64
    const int n_base = (wid & 3) * 32;    // 0,32,64,96

    float acc[4][4][4];
    #pragma unroll
    for (int i = 0; i < 4; i++)
        #pragma unroll
        for (int j = 0; j < 4; j++)
            #pragma unroll
            for (int k = 0; k < 4; k++) acc[i][j][k] = 0.f;

    auto load_stage = [&](int kk, int s) {
        const uint32_t st = sbase + s * STAGEB;
        #pragma unroll
        for (int i = 0; i < 8; i++) {
            const int idx = tid + i * 256;
            const int row = idx >> 3;          // 0..255
            const int c8  = idx & 7;
            const __half* src = (row < 128)
                ? A + (size_t)(bm + row) * DIM + kk * BK + c8 * 8
                : B + (size_t)(bn + row - 128) * DIM + kk * BK + c8 * 8;
            cp16(st + row * SA + c8 * 16, src);
        }
        CP_COMMIT();
    };

    load_stage(0, 0);
    load_stage(1, 1);

    const int lrow = lane & 15;
    const int lsel = (lane >> 4) * 16;    // 0 or 16 bytes

    for (int kk = 0; kk < NKK; kk++) {
        CP_WAIT1();
        __syncthreads();
        if (kk + 2 < NKK) load_stage(kk + 2, (kk + 2) % STAGES);
        else              CP_COMMIT();     // empty group keeps wait_group 1 sound

        const uint32_t st    = sbase + (kk % STAGES) * STAGEB;
        const uint32_t aaddr = st + (m_base + lrow) * SA + lsel;
        const uint32_t baddr = st + 128 * SA + (n_base + lrow) * SA + lsel;

        #pragma unroll
        for (int ks = 0; ks < 4; ks++) {
            uint32_t br[2][4];
            #pragma unroll
            for (int ni = 0; ni < 2; ni++) ldsm4(br[ni], baddr + ni * 16 * SA + ks * 32);

            uint32_t ar[4][4];
            #pragma unroll
            for (int mi = 0; mi < 4; mi++) ldsm4(ar[mi], aaddr + mi * 16 * SA + ks * 32);

            #pragma unroll
            for (int mi = 0; mi < 4; mi++)
                #pragma unroll
                for (int nj = 0; nj < 4; nj++)
                    mma16816h(acc[mi][nj], ar[mi],
                              br[nj >> 1][nj & 1], br[nj >> 1][2 + (nj & 1)]);
        }
    }

    const int g  = lane >> 2;
    const int t2 = (lane & 3) * 2;
    #pragma unroll
    for (int mi = 0; mi < 4; mi++) {
        const int row = bm + m_base + mi * 16 + g;
        OutT* crow = C + (size_t)row * ldc + bn + n_base + t2;
        #pragma unroll
        for (int nj = 0; nj < 4; nj++) {
            store2(crow + nj * 8,                   acc[mi][nj][0], acc[mi][nj][1]);
            store2(crow + (size_t)8 * ldc + nj * 8, acc[mi][nj][2], acc[mi][nj][3]);
        }
    }
}

// ---------------------------------------------------------------------------
// Attention v2: one warp per token, 8 tokens per 256-thread block.
// fp16 smem staging (raw uint4 copy), warp-only sync, padded rows (136 halves).
// ---------------------------------------------------------------------------
__global__ __launch_bounds__(256)
void attn_kernel(const __half* __restrict__ query,
                 const __half* __restrict__ kvproj,
                 __half* __restrict__ ctx) {
    extern __shared__ char asmem[];
    const int w    = threadIdx.x >> 5;
    const int lane = threadIdx.x & 31;
    const int t    = blockIdx.x * ATOK + w;

    __half* sq = (__half*)(asmem + w * AWSTRIDE);              // 8 rows x 136
    __half* sk = sq + 8 * AROWS;
    __half* sv = sk + 8 * AROWS;
    float*  sc = (float*)(sv + 8 * AROWS);                     // 64 floats (sc then w in-place)

    // ---- load q,k,v into padded fp16 smem (raw copies, 4 uint4 per lane each)
    {
        const uint4* qp = (const uint4*)(query + (size_t)t * DIM);
        const uint4* kp = (const uint4*)(kvproj + (size_t)t * 2 * DIM);
        const uint4* vp = kp + DIM / 8;
        #pragma unroll
        for (int i = 0; i < 4; i++) {
            const int e4  = i * 32 + lane;        // uint4 index 0..127
            const int row = e4 >> 4;              // 8 halves per uint4, 128/row
            const int col = (e4 & 15) * 8;
            *(uint4*)(sq + row * AROWS + col) = qp[e4];
            *(uint4*)(sk + row * AROWS + col) = kp[e4];
            *(uint4*)(sv + row * AROWS + col) = vp[e4];
        }
    }
    __syncwarp();

    // ---- scores: each lane computes 2 of the 64 (h,g) dot products
    #pragma unroll
    for (int pp = 0; pp < 2; pp++) {
        const int p = lane * 2 + pp;
        const int h = p >> 3, g = p & 7;
        const __half2* qq = (const __half2*)(sq + h * AROWS);
        const __half2* kk = (const __half2*)(sk + g * AROWS);
        float s = 0.f;
        #pragma unroll 16
        for (int d2 = 0; d2 < 64; d2++) {
            float2 a = __half22float2(qq[d2]);
            float2 b = __half22float2(kk[d2]);
            s += a.x * b.x + a.y * b.y;
        }
        sc[p] = s * 0.08838834764831845f;   // 1/sqrt(128)
    }
    __syncwarp();

    // ---- softmax per row (lanes 0-7), in place
    if (lane < 8) {
        float m = -1e30f;
        #pragma unroll
        for (int g = 0; g < 8; g++) m = fmaxf(m, sc[lane * 8 + g]);
        float e[8], sum = 0.f;
        #pragma unroll
        for (int g = 0; g < 8; g++) { e[g] = expf(sc[lane * 8 + g] - m); sum += e[g]; }
        const float inv = 1.0f / sum;
        #pragma unroll
        for (int g = 0; g < 8; g++) sc[lane * 8 + g] = e[g] * inv;
    }
    __syncwarp();

    // ---- context: lane handles d = lane + {0,32,64,96} for all 8 heads
    #pragma unroll
    for (int j = 0; j < 4; j++) {
        const int d = lane + j * 32;
        #pragma unroll
        for (int h = 0; h < 8; h++) {
            float a = 0.f;
            #pragma unroll
            for (int g = 0; g < 8; g++)
                a += sc[h * 8 + g] * __half2float(sv[g * AROWS + d]);
            ctx[(size_t)t * DIM + h * DHEAD + d] = __float2half_rn(a);
        }
    }
}

// ---------------------------------------------------------------------------
// Host side.  Launch order: ln(0), wconv(1), gemm1(2), gemm2(3), attn(4),
// gemm3(5) -> ncu -s 5 captures gemm3.
// ---------------------------------------------------------------------------
extern "C" void kernel_launch(void* const* d_in, const int* in_sizes, int n_in,
                              void* d_out, int out_size) {
    const float* q       = (const float*)d_in[0];
    const float* kv      = (const float*)d_in[1];
    const float* gamma_m = (const float*)d_in[2];
    const float* beta_m  = (const float*)d_in[3];
    const float* gamma_l = (const float*)d_in[4];
    const float* beta_l  = (const float*)d_in[5];
    const float* Wq      = (const float*)d_in[6];
    const float* Wkv     = (const float*)d_in[7];
    const float* Wo      = (const float*)d_in[8];
    float* out = (float*)d_out;

    void *qn, *kvn, *wq_h, *wkv_h, *wo_h, *query, *kvproj, *ctx;
    cudaGetSymbolAddress(&qn,    g_qn);     cudaGetSymbolAddress(&kvn,   g_kvn);
    cudaGetSymbolAddress(&wq_h,  g_wq_h);   cudaGetSymbolAddress(&wkv_h, g_wkv_h);
    cudaGetSymbolAddress(&wo_h,  g_wo_h);
    cudaGetSymbolAddress(&query, g_query);  cudaGetSymbolAddress(&kvproj, g_kvproj);
    cudaGetSymbolAddress(&ctx,   g_ctx);

    cudaFuncSetAttribute(gemm_fp16<__half>, cudaFuncAttributeMaxDynamicSharedMemorySize, SMEMB);
    cudaFuncSetAttribute(gemm_fp16<float>,  cudaFuncAttributeMaxDynamicSharedMemorySize, SMEMB);
    cudaFuncSetAttribute(attn_kernel,       cudaFuncAttributeMaxDynamicSharedMemorySize, ASMEM);

    // 0: fused LN for q and kv -> fp16
    ln2_kernel<<<dim3(TOKENS, 2), 256>>>(q, kv, gamma_m, beta_m, gamma_l, beta_l,
                                         (__half*)qn, (__half*)kvn);
    // 1: all weights -> fp16
    wconv_kernel<<<(4 * DIM * DIM) / 256, 256>>>(Wq, Wkv, Wo,
                                                 (__half*)wq_h, (__half*)wkv_h, (__half*)wo_h);

    // 2: query = qn @ Wq^T   [32768,1024] (fp16 out)
    gemm_fp16<__half><<<dim3(DIM / BN, TOKENS / BM), 256, SMEMB>>>(
        (const __half*)qn, (const __half*)wq_h, (__half*)query, DIM);
    // 3: kvproj = kvn @ Wkv^T  [32768,2048] (fp16 out)
    gemm_fp16<__half><<<dim3(2 * DIM / BN, TOKENS / BM), 256, SMEMB>>>(
        (const __half*)kvn, (const __half*)wkv_h, (__half*)kvproj, 2 * DIM);

    // 4: attention (warp per token)
    attn_kernel<<<TOKENS / ATOK, 256, ASMEM>>>((const __half*)query,
                                               (const __half*)kvproj, (__half*)ctx);

    // 5: out = ctx @ Wo^T   [32768,1024] (fp32 out)  <- ncu target
    gemm_fp16<float><<<dim3(DIM / BN, TOKENS / BM), 256, SMEMB>>>(
        (const __half*)ctx, (const __half*)wo_h, out, DIM);
}

// round 11
// speedup vs baseline: 3.0850x; 1.0076x over previous
#include <cuda_runtime.h>
#include <cuda_fp16.h>
#include <math.h>
#include <stdint.h>

// ---------------------------------------------------------------------------
// Problem constants
// ---------------------------------------------------------------------------
#define TOKENS   32768      // 16 * 2048
#define DIM      1024
#define HEADS    8
#define DHEAD    128
#define LN_EPS   1e-5f

// GEMM tiling: CTA 128x128, K-chunk 64, warp tile 64x64, 4 warps (2m x 2n),
// 128 threads, 2 CTAs/SM (256-reg budget -> ptxas can pipeline fragments).
#define BM       128
#define BN       128
#define BK       64
#define NKK      16           // 1024 / 64 K-chunks
#define STAGES   3
#define SA       144          // smem row stride (128B data + 16B pad)
#define ROWS_PER_STAGE (BM + BN)             // A(128) + B(128) = 256
#define STAGEB   (ROWS_PER_STAGE * SA)       // 36864
#define SMEMB    (STAGES * STAGEB)           // 110592 (x2 CTAs = 216KB/SM)

// Attention: 8 tokens per 256-thread block, one warp per token.
#define ATOK     8
#define AROWS    136                          // padded row stride in halves
#define AWSTRIDE 6912                         // 16B-aligned per-warp region
#define ASMEM    (ATOK * AWSTRIDE)            // 55296

// ---------------------------------------------------------------------------
// Scratch (device globals; cudaMalloc forbidden)
// ---------------------------------------------------------------------------
__device__ __half g_qn  [TOKENS * DIM];
__device__ __half g_kvn [TOKENS * DIM];
__device__ __half g_wq_h [DIM * DIM];
__device__ __half g_wkv_h[2 * DIM * DIM];
__device__ __half g_wo_h [DIM * DIM];
__device__ __half g_query [TOKENS * DIM];
__device__ __half g_kvproj[TOKENS * 2 * DIM];
__device__ __half g_ctx   [TOKENS * DIM];

// ---------------------------------------------------------------------------
// PTX helpers (plain sm_80-level; harness PTX target is sm_103 non-'a')
// ---------------------------------------------------------------------------
__device__ __forceinline__ uint32_t smem_u32(const void* p) {
    uint32_t a;
    asm("{ .reg .u64 t; cvta.to.shared.u64 t, %1; cvt.u32.u64 %0, t; }" : "=r"(a) : "l"(p));
    return a;
}

__device__ __forceinline__ void cp16(uint32_t dst, const void* src) {
    asm volatile("cp.async.cg.shared.global [%0], [%1], 16;" :: "r"(dst), "l"(src));
}
#define CP_COMMIT() asm volatile("cp.async.commit_group;" ::: "memory")
#define CP_WAIT1()  asm volatile("cp.async.wait_group 1;" ::: "memory")

__device__ __forceinline__ void ldsm4(uint32_t* r, uint32_t addr) {
    asm volatile("ldmatrix.sync.aligned.m8n8.x4.shared.b16 {%0,%1,%2,%3}, [%4];"
                 : "=r"(r[0]), "=r"(r[1]), "=r"(r[2]), "=r"(r[3]) : "r"(addr));
}

__device__ __forceinline__ void mma16816h(float* d, const uint32_t* a, uint32_t b0, uint32_t b1) {
    asm volatile("mma.sync.aligned.m16n8k16.row.col.f32.f16.f16.f32 "
                 "{%0,%1,%2,%3}, {%4,%5,%6,%7}, {%8,%9}, {%0,%1,%2,%3};"
                 : "+f"(d[0]), "+f"(d[1]), "+f"(d[2]), "+f"(d[3])
                 : "r"(a[0]), "r"(a[1]), "r"(a[2]), "r"(a[3]), "r"(b0), "r"(b1));
}

// epilogue store: fp32 or fp16 output
__device__ __forceinline__ void store2(float* p, float a, float b)  { *(float2*)p  = make_float2(a, b); }
__device__ __forceinline__ void store2(__half* p, float a, float b) { *(__half2*)p = __floats2half2_rn(a, b); }

// ---------------------------------------------------------------------------
// Fused LayerNorm (both q and kv) -> fp16.  grid (TOKENS, 2).
// ---------------------------------------------------------------------------
__global__ __launch_bounds__(256)
void ln2_kernel(const float* __restrict__ q,  const float* __restrict__ kv,
                const float* __restrict__ gm, const float* __restrict__ bm,
                const float* __restrict__ gl, const float* __restrict__ bl,
                __half* __restrict__ qn, __half* __restrict__ kvn) {
    const int row = blockIdx.x;
    const int sel = blockIdx.y;
    const float* x     = sel ? kv : q;
    const float* gamma = sel ? gl : gm;
    const float* beta  = sel ? bl : bm;
    __half* y = sel ? kvn : qn;

    const int tid = threadIdx.x;
    float4 v = ((const float4*)(x + (size_t)row * DIM))[tid];

    float s  = v.x + v.y + v.z + v.w;
    float sq = v.x * v.x + v.y * v.y + v.z * v.z + v.w * v.w;
    #pragma unroll
    for (int o = 16; o > 0; o >>= 1) {
        s  += __shfl_xor_sync(0xffffffffu, s,  o);
        sq += __shfl_xor_sync(0xffffffffu, sq, o);
    }
    __shared__ float rs[8], rq[8];
    const int wid = tid >> 5, lane = tid & 31;
    if (lane == 0) { rs[wid] = s; rq[wid] = sq; }
    __syncthreads();
    float tot = 0.f, totq = 0.f;
    #pragma unroll
    for (int i = 0; i < 8; i++) { tot += rs[i]; totq += rq[i]; }

    const float mu   = tot * (1.0f / DIM);
    const float var  = totq * (1.0f / DIM) - mu * mu;
    const float rinv = rsqrtf(var + LN_EPS);

    float4 g = ((const float4*)gamma)[tid];
    float4 b = ((const float4*)beta)[tid];
    float o0 = (v.x - mu) * rinv * g.x + b.x;
    float o1 = (v.y - mu) * rinv * g.y + b.y;
    float o2 = (v.z - mu) * rinv * g.z + b.z;
    float o3 = (v.w - mu) * rinv * g.w + b.w;

    __half2* yp = (__half2*)(y + (size_t)row * DIM);
    yp[2 * tid]     = __floats2half2_rn(o0, o1);
    yp[2 * tid + 1] = __floats2half2_rn(o2, o3);
}

// ---------------------------------------------------------------------------
// All three weights -> fp16 in one launch
// ---------------------------------------------------------------------------
__global__ __launch_bounds__(256)
void wconv_kernel(const float* __restrict__ Wq, const float* __restrict__ Wkv,
                  const float* __restrict__ Wo,
                  __half* __restrict__ wq, __half* __restrict__ wkv, __half* __restrict__ wo) {
    const int i = blockIdx.x * 256 + threadIdx.x;    // 0 .. 4*DIM*DIM-1
    if (i < DIM * DIM)               wq[i]                 = __float2half_rn(Wq[i]);
    else if (i < 3 * DIM * DIM)      wkv[i - DIM * DIM]    = __float2half_rn(Wkv[i - DIM * DIM]);
    else                             wo[i - 3 * DIM * DIM] = __float2half_rn(Wo[i - 3 * DIM * DIM]);
}

// ---------------------------------------------------------------------------
// fp16 GEMM:  C[M,N] = A[M,K] * B[N,K]^T, fp32 accum.
// CTA 128x128, 4 warps of 64x64 (2m x 2n), 3-stage cp.async, 2 CTAs/SM.
// 128 threads -> 256-reg budget: acc 128 + frags fit with pipelining headroom.
// ---------------------------------------------------------------------------
template <typename OutT>
__global__ __launch_bounds__(128, 2)
void gemm_fp16(const __half* __restrict__ A, const __half* __restrict__ B,
               OutT* __restrict__ C, int ldc) {
    extern __shared__ char smem[];
    const uint32_t sbase = smem_u32(smem);
    const int tid  = threadIdx.x;
    const int wid  = tid >> 5;            // 0..3
    const int lane = tid & 31;
    const int bm = blockIdx.y * BM;
    const int bn = blockIdx.x * BN;
    const int m_base = (wid >> 1) * 64;   // 0 or 64
    const int n_base = (wid & 1) * 64;    // 0 or 64

    float acc[4][8][4];
    #pragma unroll
    for (int i = 0; i < 4; i++)
        #pragma unroll
        for (int j = 0; j < 8; j++)
            #pragma unroll
            for (int k = 0; k < 4; k++) acc[i][j][k] = 0.f;

    // stage loader: 256 rows x 128B, 16B per cp.async, 16 per thread
    auto load_stage = [&](int kk, int s) {
        const uint32_t st = sbase + s * STAGEB;
        #pragma unroll
        for (int i = 0; i < 16; i++) {
            const int idx = tid + i * 128;
            const int row = idx >> 3;          // 0..255
            const int c8  = idx & 7;
            const __half* src = (row < 128)
                ? A + (size_t)(bm + row) * DIM + kk * BK + c8 * 8
                : B + (size_t)(bn + row - 128) * DIM + kk * BK + c8 * 8;
            cp16(st + row * SA + c8 * 16, src);
        }
        CP_COMMIT();
    };

    load_stage(0, 0);
    load_stage(1, 1);

    const int lrow = lane & 15;
    const int lsel = (lane >> 4) * 16;    // 0 or 16 bytes

    for (int kk = 0; kk < NKK; kk++) {
        CP_WAIT1();
        __syncthreads();
        if (kk + 2 < NKK) load_stage(kk + 2, (kk + 2) % STAGES);
        else              CP_COMMIT();     // empty group keeps wait_group 1 sound

        const uint32_t st    = sbase + (kk % STAGES) * STAGEB;
        const uint32_t aaddr = st + (m_base + lrow) * SA + lsel;
        const uint32_t baddr = st + 128 * SA + (n_base + lrow) * SA + lsel;

        #pragma unroll
        for (int ks = 0; ks < 4; ks++) {
            uint32_t br[4][4];
            #pragma unroll
            for (int ni = 0; ni < 4; ni++) ldsm4(br[ni], baddr + ni * 16 * SA + ks * 32);

            uint32_t ar[4][4];
            #pragma unroll
            for (int mi = 0; mi < 4; mi++) ldsm4(ar[mi], aaddr + mi * 16 * SA + ks * 32);

            #pragma unroll
            for (int mi = 0; mi < 4; mi++)
                #pragma unroll
                for (int nj = 0; nj < 8; nj++)
                    mma16816h(acc[mi][nj], ar[mi],
                              br[nj >> 1][nj & 1], br[nj >> 1][2 + (nj & 1)]);
        }
    }

    // epilogue
    const int g  = lane >> 2;
    const int t2 = (lane & 3) * 2;
    #pragma unroll
    for (int mi = 0; mi < 4; mi++) {
        const int row = bm + m_base + mi * 16 + g;
        OutT* crow = C + (size_t)row * ldc + bn + n_base + t2;
        #pragma unroll
        for (int nj = 0; nj < 8; nj++) {
            store2(crow + nj * 8,                   acc[mi][nj][0], acc[mi][nj][1]);
            store2(crow + (size_t)8 * ldc + nj * 8, acc[mi][nj][2], acc[mi][nj][3]);
        }
    }
}

// ---------------------------------------------------------------------------
// Attention: one warp per token, 8 tokens per 256-thread block. (round-10)
// ---------------------------------------------------------------------------
__global__ __launch_bounds__(256)
void attn_kernel(const __half* __restrict__ query,
                 const __half* __restrict__ kvproj,
                 __half* __restrict__ ctx) {
    extern __shared__ char asmem[];
    const int w    = threadIdx.x >> 5;
    const int lane = threadIdx.x & 31;
    const int t    = blockIdx.x * ATOK + w;

    __half* sq = (__half*)(asmem + w * AWSTRIDE);              // 8 rows x 136
    __half* sk = sq + 8 * AROWS;
    __half* sv = sk + 8 * AROWS;
    float*  sc = (float*)(sv + 8 * AROWS);                     // 64 floats

    {
        const uint4* qp = (const uint4*)(query + (size_t)t * DIM);
        const uint4* kp = (const uint4*)(kvproj + (size_t)t * 2 * DIM);
        const uint4* vp = kp + DIM / 8;
        #pragma unroll
        for (int i = 0; i < 4; i++) {
            const int e4  = i * 32 + lane;        // uint4 index 0..127
            const int row = e4 >> 4;
            const int col = (e4 & 15) * 8;
            *(uint4*)(sq + row * AROWS + col) = qp[e4];
            *(uint4*)(sk + row * AROWS + col) = kp[e4];
            *(uint4*)(sv + row * AROWS + col) = vp[e4];
        }
    }
    __syncwarp();

    #pragma unroll
    for (int pp = 0; pp < 2; pp++) {
        const int p = lane * 2 + pp;
        const int h = p >> 3, g = p & 7;
        const __half2* qq = (const __half2*)(sq + h * AROWS);
        const __half2* kk = (const __half2*)(sk + g * AROWS);
        float s = 0.f;
        #pragma unroll 16
        for (int d2 = 0; d2 < 64; d2++) {
            float2 a = __half22float2(qq[d2]);
            float2 b = __half22float2(kk[d2]);
            s += a.x * b.x + a.y * b.y;
        }
        sc[p] = s * 0.08838834764831845f;   // 1/sqrt(128)
    }
    __syncwarp();

    if (lane < 8) {
        float m = -1e30f;
        #pragma unroll
        for (int g = 0; g < 8; g++) m = fmaxf(m, sc[lane * 8 + g]);
        float e[8], sum = 0.f;
        #pragma unroll
        for (int g = 0; g < 8; g++) { e[g] = expf(sc[lane * 8 + g] - m); sum += e[g]; }
        const float inv = 1.0f / sum;
        #pragma unroll
        for (int g = 0; g < 8; g++) sc[lane * 8 + g] = e[g] * inv;
    }
    __syncwarp();

    #pragma unroll
    for (int j = 0; j < 4; j++) {
        const int d = lane + j * 32;
        #pragma unroll
        for (int h = 0; h < 8; h++) {
            float a = 0.f;
            #pragma unroll
            for (int g = 0; g < 8; g++)
                a += sc[h * 8 + g] * __half2float(sv[g * AROWS + d]);
            ctx[(size_t)t * DIM + h * DHEAD + d] = __float2half_rn(a);
        }
    }
}

// ---------------------------------------------------------------------------
// Host side.  Launch order: ln(0), wconv(1), gemm1(2), gemm2(3), attn(4),
// gemm3(5) -> ncu -s 5 captures gemm3.
// ---------------------------------------------------------------------------
extern "C" void kernel_launch(void* const* d_in, const int* in_sizes, int n_in,
                              void* d_out, int out_size) {
    const float* q       = (const float*)d_in[0];
    const float* kv      = (const float*)d_in[1];
    const float* gamma_m = (const float*)d_in[2];
    const float* beta_m  = (const float*)d_in[3];
    const float* gamma_l = (const float*)d_in[4];
    const float* beta_l  = (const float*)d_in[5];
    const float* Wq      = (const float*)d_in[6];
    const float* Wkv     = (const float*)d_in[7];
    const float* Wo      = (const float*)d_in[8];
    float* out = (float*)d_out;

    void *qn, *kvn, *wq_h, *wkv_h, *wo_h, *query, *kvproj, *ctx;
    cudaGetSymbolAddress(&qn,    g_qn);     cudaGetSymbolAddress(&kvn,   g_kvn);
    cudaGetSymbolAddress(&wq_h,  g_wq_h);   cudaGetSymbolAddress(&wkv_h, g_wkv_h);
    cudaGetSymbolAddress(&wo_h,  g_wo_h);
    cudaGetSymbolAddress(&query, g_query);  cudaGetSymbolAddress(&kvproj, g_kvproj);
    cudaGetSymbolAddress(&ctx,   g_ctx);

    cudaFuncSetAttribute(gemm_fp16<__half>, cudaFuncAttributeMaxDynamicSharedMemorySize, SMEMB);
    cudaFuncSetAttribute(gemm_fp16<float>,  cudaFuncAttributeMaxDynamicSharedMemorySize, SMEMB);
    cudaFuncSetAttribute(attn_kernel,       cudaFuncAttributeMaxDynamicSharedMemorySize, ASMEM);

    // 0: fused LN for q and kv -> fp16
    ln2_kernel<<<dim3(TOKENS, 2), 256>>>(q, kv, gamma_m, beta_m, gamma_l, beta_l,
                                         (__half*)qn, (__half*)kvn);
    // 1: all weights -> fp16
    wconv_kernel<<<(4 * DIM * DIM) / 256, 256>>>(Wq, Wkv, Wo,
                                                 (__half*)wq_h, (__half*)wkv_h, (__half*)wo_h);

    // 2: query = qn @ Wq^T   [32768,1024] (fp16 out)
    gemm_fp16<__half><<<dim3(DIM / BN, TOKENS / BM), 128, SMEMB>>>(
        (const __half*)qn, (const __half*)wq_h, (__half*)query, DIM);
    // 3: kvproj = kvn @ Wkv^T  [32768,2048] (fp16 out)
    gemm_fp16<__half><<<dim3(2 * DIM / BN, TOKENS / BM), 128, SMEMB>>>(
        (const __half*)kvn, (const __half*)wkv_h, (__half*)kvproj, 2 * DIM);

    // 4: attention (warp per token)
    attn_kernel<<<TOKENS / ATOK, 256, ASMEM>>>((const __half*)query,
                                               (const __half*)kvproj, (__half*)ctx);

    // 5: out = ctx @ Wo^T   [32768,1024] (fp32 out)  <- ncu target
    gemm_fp16<float><<<dim3(DIM / BN, TOKENS / BM), 128, SMEMB>>>(
        (const __half*)ctx, (const __half*)wo_h, out, DIM);
}